// round 8
// baseline (speedup 1.0000x reference)
#include <cuda_runtime.h>
#include <math.h>

#define BB    64
#define NNODE 1024
#define FIN   195
#define HH    128
#define OO    64
#define KK1   512
#define KK2   256
#define QW    64      // padded words per row (256 int8)
#define QWU   49      // used words: ceil(195/4)

// ---------------- scratch (device globals; no allocation allowed) ----------------
__device__ unsigned       g_q8[(size_t)BB*NNODE*QW];
__device__ float          g_s[BB*NNODE];
__device__ unsigned char  g_A[(size_t)BB*NNODE*NNODE];
__device__ unsigned short g_nbr[(size_t)BB*NNODE*NNODE];
__device__ int            g_deg[BB*NNODE];
__device__ float          g_U[(size_t)BB*NNODE*HH];
__device__ float          g_V[(size_t)BB*NNODE*HH];
__device__ float          g_h1[(size_t)BB*NNODE*HH];
__device__ float          g_srel[BB*NNODE];
__device__ float          g_sroot[BB*NNODE];
__device__ float          g_score[BB*NNODE];
__device__ int            g_idx1[BB*KK1];
__device__ float          g_x1[(size_t)BB*KK1*HH];
__device__ unsigned short g_nbr2[(size_t)BB*KK1*KK1];
__device__ int            g_deg2[BB*KK1];
__device__ float          g_U2[(size_t)BB*KK1*OO];
__device__ float          g_V2[(size_t)BB*KK1*OO];
__device__ float          g_h2[(size_t)BB*KK1*OO];
__device__ float          g_srel2[BB*KK1];
__device__ float          g_sroot2[BB*KK1];
__device__ float          g_score2[BB*KK1];
__device__ int            g_idx2[BB*KK2];
__device__ float          g_tanh2[BB*KK2];
__device__ float          g_pool[BB*OO];

// ---------------- 1) center + normalize + int8 quantize (warp per row) ----------------
__global__ void k_center_q8(const float* __restrict__ x) {
    int row = blockIdx.x * 8 + (threadIdx.x >> 5);
    int lane = threadIdx.x & 31;
    const float* xr = x + (size_t)row * FIN;
    float v[8];
    float sum = 0.f;
#pragma unroll
    for (int j = 0; j < 8; j++) {
        int f = lane * 8 + j;
        v[j] = (f < FIN) ? xr[f] : 0.f;
        sum += v[j];
    }
#pragma unroll
    for (int o = 16; o; o >>= 1) sum += __shfl_xor_sync(0xffffffffu, sum, o);
    float mean = sum * (1.0f / FIN);
    float ssq = 0.f;
#pragma unroll
    for (int j = 0; j < 8; j++) {
        int f = lane * 8 + j;
        float c = (f < FIN) ? (v[j] - mean) : 0.f;
        v[j] = c;
        ssq += c * c;
    }
#pragma unroll
    for (int o = 16; o; o >>= 1) ssq += __shfl_xor_sync(0xffffffffu, ssq, o);
    float rinv = rsqrtf(fmaxf(ssq, 1e-12f));
    float mx = 0.f;
#pragma unroll
    for (int j = 0; j < 8; j++) {
        v[j] *= rinv;
        mx = fmaxf(mx, fabsf(v[j]));
    }
#pragma unroll
    for (int o = 16; o; o >>= 1) mx = fmaxf(mx, __shfl_xor_sync(0xffffffffu, mx, o));
    float s = (mx > 0.f) ? 127.f / mx : 0.f;
    int q[8];
#pragma unroll
    for (int j = 0; j < 8; j++) {
        int t = __float2int_rn(v[j] * s);
        q[j] = max(-127, min(127, t));
    }
    unsigned w0 = (q[0] & 0xff) | ((q[1] & 0xff) << 8) | ((q[2] & 0xff) << 16) | ((q[3] & 0xff) << 24);
    unsigned w1 = (q[4] & 0xff) | ((q[5] & 0xff) << 8) | ((q[6] & 0xff) << 16) | ((q[7] & 0xff) << 24);
    unsigned long long pw = (unsigned long long)w0 | ((unsigned long long)w1 << 32);
    *(unsigned long long*)(g_q8 + (size_t)row * QW + lane * 2) = pw;
    if (lane == 0) g_s[row] = s;
}

// ---------------- 2) cov via DP4A int8: A = (dot > 0.5*s_i*s_j) ----------------
#define COV_LDW 132
#define COV_SMEM (2 * QW * COV_LDW * 4)   // 67584 B

__global__ void __launch_bounds__(256) k_cov_dp4a(unsigned char* __restrict__ Aout) {
    extern __shared__ unsigned covsm[];
    unsigned* As = covsm;
    unsigned* Bs = covsm + QW * COV_LDW;
    int b = blockIdx.z, bi = blockIdx.x, bj = blockIdx.y;
    if (bj < bi) return;
    int tid = threadIdx.x, tx = tid & 15, ty = tid >> 4;

    const unsigned* qb = g_q8 + (size_t)b * NNODE * QW;
#pragma unroll
    for (int half = 0; half < 2; half++) {
        int rowoff = (half ? bj : bi) * 128;
        unsigned* dst = half ? Bs : As;
        const unsigned* src = qb + (size_t)rowoff * QW;
#pragma unroll
        for (int p = 0; p < 32; p++) {
            int e = tid + p * 256;
            int i = e >> 6, k = e & 63;
            if (k < QWU) dst[k * COV_LDW + i] = src[i * QW + k];
        }
    }
    __syncthreads();

    int acc[8][8];
#pragma unroll
    for (int r = 0; r < 8; r++)
#pragma unroll
        for (int c = 0; c < 8; c++) acc[r][c] = 0;

    for (int kw = 0; kw < QWU; kw++) {          // only the 49 non-zero words
        int a[8], bv[8];
        const unsigned* ap = As + kw * COV_LDW + ty * 8;
        const unsigned* bp = Bs + kw * COV_LDW + tx * 8;
#pragma unroll
        for (int r = 0; r < 8; r++) a[r] = (int)ap[r];
#pragma unroll
        for (int c = 0; c < 8; c++) bv[c] = (int)bp[c];
#pragma unroll
        for (int r = 0; r < 8; r++)
#pragma unroll
            for (int c = 0; c < 8; c++)
                acc[r][c] = __dp4a(a[r], bv[c], acc[r][c]);
    }

    __syncthreads();
    unsigned char* Bt = (unsigned char*)covsm;       // [128][132] bytes
    const float* sb = g_s + b * NNODE;
    float si[8], sj[8];
#pragma unroll
    for (int r = 0; r < 8; r++) si[r] = sb[bi * 128 + ty * 8 + r];
#pragma unroll
    for (int c = 0; c < 8; c++) sj[c] = sb[bj * 128 + tx * 8 + c];
#pragma unroll
    for (int r = 0; r < 8; r++) {
        float hs = 0.5f * si[r];
#pragma unroll
        for (int c = 0; c < 8; c++)
            Bt[(ty * 8 + r) * COV_LDW + tx * 8 + c] =
                ((float)acc[r][c] > hs * sj[c]) ? 1 : 0;
    }
    __syncthreads();

    {
        int r = tid >> 1, half = (tid & 1) * 64;
        unsigned char* arow = Aout + ((size_t)b * NNODE + bi * 128 + r) * NNODE + bj * 128 + half;
        const unsigned char* srow = Bt + r * COV_LDW + half;
#pragma unroll
        for (int g = 0; g < 4; g++) {
            uint4 vv;
            vv.x = *(const unsigned*)(srow + g * 16 + 0);
            vv.y = *(const unsigned*)(srow + g * 16 + 4);
            vv.z = *(const unsigned*)(srow + g * 16 + 8);
            vv.w = *(const unsigned*)(srow + g * 16 + 12);
            *(uint4*)(arow + g * 16) = vv;
        }
    }
    if (bi != bj) {
        int r = tid >> 1, half = (tid & 1) * 64;
        unsigned char* arow = Aout + ((size_t)b * NNODE + bj * 128 + r) * NNODE + bi * 128 + half;
#pragma unroll
        for (int g = 0; g < 16; g++) {
            unsigned wv = 0;
#pragma unroll
            for (int k2 = 0; k2 < 4; k2++)
                wv |= (unsigned)Bt[(half + g * 4 + k2) * COV_LDW + r] << (8 * k2);
            *(unsigned*)(arow + g * 4) = wv;
        }
    }
}

// ---------------- 3) compact adjacency rows (u32 loads + warp scan) ----------------
__global__ void k_compact(const unsigned char* __restrict__ A, unsigned short* __restrict__ nbr,
                          int* __restrict__ deg, int Nn, int rows) {
    int warp = (blockIdx.x * blockDim.x + threadIdx.x) >> 5;
    int lane = threadIdx.x & 31;
    if (warp >= rows) return;
    const unsigned* ar = (const unsigned*)(A + (size_t)warp * Nn);
    unsigned short* nr = nbr + (size_t)warp * Nn;
    int base = 0;
    for (int it = 0; it < Nn / 128; it++) {
        int w = it * 32 + lane;
        unsigned u = ar[w];
        int c0 = (u & 0xffu) != 0, c1 = (u & 0xff00u) != 0,
            c2 = (u & 0xff0000u) != 0, c3 = (u & 0xff000000u) != 0;
        int cnt = c0 + c1 + c2 + c3;
        int incl = cnt;
#pragma unroll
        for (int o = 1; o < 32; o <<= 1) {
            int t = __shfl_up_sync(0xffffffffu, incl, o);
            if (lane >= o) incl += t;
        }
        int pos = base + incl - cnt;
        int col = w * 4;
        if (c0) nr[pos++] = (unsigned short)(col + 0);
        if (c1) nr[pos++] = (unsigned short)(col + 1);
        if (c2) nr[pos++] = (unsigned short)(col + 2);
        if (c3) nr[pos++] = (unsigned short)(col + 3);
        base += __shfl_sync(0xffffffffu, incl, 31);
    }
    if (lane == 0) deg[warp] = base;
}

// ---------------- 4a) fused U/V GEMM: out = X*W^T, 128x128 tile, double-buffered ----------------
__global__ void __launch_bounds__(256) k_gemmNT128_uv(
        const float* __restrict__ X, const float* __restrict__ W0,
        const float* __restrict__ W1, float* __restrict__ U, float* __restrict__ V, int K) {
    __shared__ float As[2][8][136];
    __shared__ float Bs[2][8][136];
    const float* W = blockIdx.y ? W1 : W0;
    float* Out = blockIdx.y ? V : U;
    int bx = blockIdx.x;
    int tid = threadIdx.x, tx = tid & 15, ty = tid >> 4;
    float acc[8][8];
#pragma unroll
    for (int r = 0; r < 8; r++)
#pragma unroll
        for (int c = 0; c < 8; c++) acc[r][c] = 0.f;

    const int nk = (K + 7) / 8;   // 25 for K=195

    // prologue: stage k-block 0 into buffer 0
#pragma unroll
    for (int r = 0; r < 4; r++) {
        int e = tid + r * 256;
        int i = e >> 3, k = e & 7;
        float va = (k < K) ? X[(size_t)(bx * 128 + i) * K + k] : 0.f;
        float vb = (k < K) ? W[(size_t)i * K + k] : 0.f;
        As[0][k][i] = va; Bs[0][k][i] = vb;
    }
    __syncthreads();

    for (int t = 0; t < nk; t++) {
        int cur = t & 1, nxt = cur ^ 1;
        if (t + 1 < nk) {
            int kk = (t + 1) * 8;
#pragma unroll
            for (int r = 0; r < 4; r++) {
                int e = tid + r * 256;
                int i = e >> 3, k = e & 7;
                float va = 0.f, vb = 0.f;
                if (kk + k < K) {
                    va = X[(size_t)(bx * 128 + i) * K + kk + k];
                    vb = W[(size_t)i * K + kk + k];
                }
                As[nxt][k][i] = va; Bs[nxt][k][i] = vb;
            }
        }
#pragma unroll
        for (int k = 0; k < 8; k++) {
            float a[8], bv[8];
#pragma unroll
            for (int r = 0; r < 8; r++) a[r] = As[cur][k][ty * 8 + r];
#pragma unroll
            for (int c = 0; c < 8; c++) bv[c] = Bs[cur][k][tx * 8 + c];
#pragma unroll
            for (int r = 0; r < 8; r++)
#pragma unroll
                for (int c = 0; c < 8; c++) acc[r][c] = fmaf(a[r], bv[c], acc[r][c]);
        }
        __syncthreads();
    }
#pragma unroll
    for (int r = 0; r < 8; r++) {
        int gi = bx * 128 + ty * 8 + r;
#pragma unroll
        for (int c = 0; c < 8; c++)
            Out[(size_t)gi * 128 + tx * 8 + c] = acc[r][c];
    }
}

// ---------------- 4b) fused U2/V2 GEMM: out[M x 64] = X[M x 128] * W^T, 64x64 tile ----------------
__global__ void k_gemmNT64_uv(const float* __restrict__ X, const float* __restrict__ W0,
                              const float* __restrict__ W1,
                              float* __restrict__ U, float* __restrict__ V) {
    __shared__ float As[16][68];
    __shared__ float Bs[16][68];
    const float* W = blockIdx.y ? W1 : W0;
    float* Out = blockIdx.y ? V : U;
    int bx = blockIdx.x;
    int tid = threadIdx.x, tx = tid & 15, ty = tid >> 4;
    float acc[4][4];
#pragma unroll
    for (int r = 0; r < 4; r++)
#pragma unroll
        for (int c = 0; c < 4; c++) acc[r][c] = 0.f;

    for (int kk = 0; kk < HH; kk += 16) {
#pragma unroll
        for (int r = 0; r < 4; r++) {
            int e = tid + r * 256;
            int i = e >> 4, k = e & 15;
            As[k][i] = X[(size_t)(bx * 64 + i) * HH + kk + k];
            Bs[k][i] = (i < OO) ? W[(size_t)i * HH + kk + k] : 0.f;
        }
        __syncthreads();
#pragma unroll
        for (int k = 0; k < 16; k++) {
            float a[4], bv[4];
#pragma unroll
            for (int r = 0; r < 4; r++) a[r] = As[k][ty * 4 + r];
#pragma unroll
            for (int c = 0; c < 4; c++) bv[c] = Bs[k][tx * 4 + c];
#pragma unroll
            for (int r = 0; r < 4; r++)
#pragma unroll
                for (int c = 0; c < 4; c++) acc[r][c] = fmaf(a[r], bv[c], acc[r][c]);
        }
        __syncthreads();
    }
#pragma unroll
    for (int r = 0; r < 4; r++) {
        int gi = bx * 64 + ty * 4 + r;
#pragma unroll
        for (int c = 0; c < 4; c++) {
            int gj = tx * 4 + c;
            if (gj < OO) Out[(size_t)gi * OO + gj] = acc[r][c];
        }
    }
}

// ---------------- 5) post-aggregate stage1: h1 = relu(meanN(U) + b + V); + score pre ----------------
__global__ void k_postagg1(const float* __restrict__ bias,
                           const float* __restrict__ Wrel, const float* __restrict__ Wroot) {
    int row = blockIdx.x * 8 + (threadIdx.x >> 5);
    int lane = threadIdx.x & 31;
    int b = row >> 10;
    int dg = g_deg[row];
    const unsigned short* nr = g_nbr + (size_t)row * NNODE;
    float acc[4] = {0.f, 0.f, 0.f, 0.f};
    for (int c = 0; c < dg; c++) {
        const float* Ur = g_U + ((size_t)(b * NNODE + nr[c])) * HH;
#pragma unroll
        for (int k = 0; k < 4; k++) acc[k] += Ur[lane + 32 * k];
    }
    float inv = 1.f / fmaxf((float)dg, 1.f);
    const float* Vr = g_V + (size_t)row * HH;
    float* hr = g_h1 + (size_t)row * HH;
    float sa = 0.f, sr = 0.f;
#pragma unroll
    for (int k = 0; k < 4; k++) {
        int f = lane + 32 * k;
        float h = fmaxf(acc[k] * inv + bias[f] + Vr[f], 0.f);
        hr[f] = h;
        sa = fmaf(h, Wrel[f], sa);
        sr = fmaf(h, Wroot[f], sr);
    }
#pragma unroll
    for (int o = 16; o; o >>= 1) {
        sa += __shfl_down_sync(0xffffffffu, sa, o);
        sr += __shfl_down_sync(0xffffffffu, sr, o);
    }
    if (lane == 0) { g_srel[row] = sa; g_sroot[row] = sr; }
}

// ---------------- 5b) post-aggregate stage2 (F=64) ----------------
__global__ void k_postagg2(const float* __restrict__ bias,
                           const float* __restrict__ Wrel, const float* __restrict__ Wroot) {
    int row = blockIdx.x * 8 + (threadIdx.x >> 5);
    int lane = threadIdx.x & 31;
    int b = row / KK1;
    int dg = g_deg2[row];
    const unsigned short* nr = g_nbr2 + (size_t)row * KK1;
    float acc[2] = {0.f, 0.f};
    for (int c = 0; c < dg; c++) {
        const float* Ur = g_U2 + ((size_t)(b * KK1 + nr[c])) * OO;
#pragma unroll
        for (int k = 0; k < 2; k++) acc[k] += Ur[lane + 32 * k];
    }
    float inv = 1.f / fmaxf((float)dg, 1.f);
    const float* Vr = g_V2 + (size_t)row * OO;
    float* hr = g_h2 + (size_t)row * OO;
    float sa = 0.f, sr = 0.f;
#pragma unroll
    for (int k = 0; k < 2; k++) {
        int f = lane + 32 * k;
        float h = fmaxf(acc[k] * inv + bias[f] + Vr[f], 0.f);
        hr[f] = h;
        sa = fmaf(h, Wrel[f], sa);
        sr = fmaf(h, Wroot[f], sr);
    }
#pragma unroll
    for (int o = 16; o; o >>= 1) {
        sa += __shfl_down_sync(0xffffffffu, sa, o);
        sr += __shfl_down_sync(0xffffffffu, sr, o);
    }
    if (lane == 0) { g_srel2[row] = sa; g_sroot2[row] = sr; }
}

// ---------------- 6) score = sum_{m in N(n)} srel[m] + brel + sroot[n] ----------------
__global__ void k_score_agg(const float* __restrict__ srel, const float* __restrict__ sroot,
                            const unsigned short* __restrict__ nbr, const int* __restrict__ deg,
                            const float* __restrict__ brel, float* __restrict__ score,
                            int Nn, int rows) {
    int warp = (blockIdx.x * blockDim.x + threadIdx.x) >> 5;
    int lane = threadIdx.x & 31;
    if (warp >= rows) return;
    int b = warp / Nn;
    int dg = deg[warp];
    const unsigned short* nr = nbr + (size_t)warp * Nn;
    float a = 0.f;
    for (int c = lane; c < dg; c += 32) a += srel[b * Nn + nr[c]];
    for (int o = 16; o; o >>= 1) a += __shfl_down_sync(0xffffffffu, a, o);
    if (lane == 0) score[warp] = a + brel[0] + sroot[warp];
}

// ---------------- bitonic sort (descending, tie -> smaller idx) ----------------
__device__ __forceinline__ bool prec_cmp(float sa, int ia, float sb, int ib) {
    return (sa > sb) || (sa == sb && ia < ib);
}

template <int NSORT>
__device__ void bitonic_sort(float* s, int* id, int t) {
    for (int k = 2; k <= NSORT; k <<= 1) {
        for (int j = k >> 1; j > 0; j >>= 1) {
            int ixj = t ^ j;
            if (ixj > t) {
                float s1 = s[t], s2 = s[ixj];
                int   i1 = id[t], i2 = id[ixj];
                bool sw;
                if ((t & k) == 0) sw = prec_cmp(s2, i2, s1, i1);
                else              sw = prec_cmp(s1, i1, s2, i2);
                if (sw) { s[t] = s2; s[ixj] = s1; id[t] = i2; id[ixj] = i1; }
            }
            __syncthreads();
        }
    }
}

// ---------------- 7) top-k pool1 + gather x1 ----------------
__global__ void k_topk1(const float* __restrict__ score) {
    __shared__ float s[NNODE];
    __shared__ int   id[NNODE];
    int b = blockIdx.x, t = threadIdx.x;
    s[t] = score[b * NNODE + t];
    id[t] = t;
    __syncthreads();
    bitonic_sort<NNODE>(s, id, t);
    if (t < KK1) {
        g_idx1[b * KK1 + t] = id[t];
        s[t] = tanhf(s[t]);
    }
    __syncthreads();
    const float* h1b = g_h1 + (size_t)b * NNODE * HH;
    float* x1b = g_x1 + (size_t)b * KK1 * HH;
    for (int e = t; e < KK1 * HH; e += NNODE) {
        int k = e >> 7;
        int f = e & 127;
        x1b[e] = h1b[(size_t)id[k] * HH + f] * s[k];
    }
}

// ---------------- 8) fused: nbr2/deg2 directly from A + idx1 ----------------
__global__ void k_nbr2() {
    int b = blockIdx.y;
    int wid = threadIdx.x >> 5, lane = threadIdx.x & 31;
    int i = blockIdx.x * 8 + wid;
    __shared__ int sidx[KK1];
    for (int e = threadIdx.x; e < KK1; e += 256) sidx[e] = g_idx1[b * KK1 + e];
    __syncthreads();
    const unsigned char* ar = g_A + ((size_t)b * NNODE + sidx[i]) * NNODE;
    unsigned short* nr = g_nbr2 + ((size_t)b * KK1 + i) * KK1;
    int cnt = 0;
    for (int base = 0; base < KK1; base += 32) {
        int jj = base + lane;
        unsigned char a = ar[sidx[jj]];
        unsigned mask = __ballot_sync(0xffffffffu, a != 0);
        if (a) nr[cnt + __popc(mask & ((1u << lane) - 1u))] = (unsigned short)jj;
        cnt += __popc(mask);
    }
    if (lane == 0) g_deg2[b * KK1 + i] = cnt;
}

// ---------------- 9) top-k pool2 ----------------
__global__ void k_topk2(const float* __restrict__ score) {
    __shared__ float s[KK1];
    __shared__ int   id[KK1];
    int b = blockIdx.x, t = threadIdx.x;
    s[t] = score[b * KK1 + t];
    id[t] = t;
    __syncthreads();
    bitonic_sort<KK1>(s, id, t);
    if (t < KK2) {
        g_idx2[b * KK2 + t] = id[t];
        g_tanh2[b * KK2 + t] = tanhf(s[t]);
    }
}

// ---------------- 10) gather + scale + global mean pool ----------------
__global__ void k_pool_mean() {
    int b = blockIdx.x, f = threadIdx.x;   // 64 threads
    const float* h2b = g_h2 + (size_t)b * KK1 * OO;
    float acc = 0.f;
    for (int k = 0; k < KK2; k++)
        acc += h2b[(size_t)g_idx2[b * KK2 + k] * OO + f] * g_tanh2[b * KK2 + k];
    g_pool[b * OO + f] = acc * (1.f / KK2);
}

// ---------------- 11) MLP head ----------------
__global__ void k_mlp(const float* __restrict__ fc1_w, const float* __restrict__ fc1_b,
                      const float* __restrict__ g1, const float* __restrict__ b1,
                      const float* __restrict__ m1, const float* __restrict__ v1,
                      const float* __restrict__ fc2_w, const float* __restrict__ fc2_b,
                      const float* __restrict__ g2, const float* __restrict__ b2,
                      const float* __restrict__ m2, const float* __restrict__ v2,
                      const float* __restrict__ fc3_w, const float* __restrict__ fc3_b,
                      float* __restrict__ out) {
    int b = blockIdx.x, t = threadIdx.x;   // 512 threads
    __shared__ float sin[OO];
    __shared__ float a1[512];
    __shared__ float a2[256];
    __shared__ float lg[2];
    if (t < OO) sin[t] = g_pool[b * OO + t];
    __syncthreads();
    {
        float acc = fc1_b[t];
        const float* w = fc1_w + (size_t)t * OO;
        for (int k = 0; k < OO; k++) acc = fmaf(sin[k], w[k], acc);
        acc = fmaxf(acc, 0.f);
        a1[t] = g1[t] * (acc - m1[t]) * rsqrtf(v1[t] + 1e-5f) + b1[t];
    }
    __syncthreads();
    if (t < 256) {
        float acc = fc2_b[t];
        const float* w = fc2_w + (size_t)t * 512;
        for (int k = 0; k < 512; k++) acc = fmaf(a1[k], w[k], acc);
        acc = fmaxf(acc, 0.f);
        a2[t] = g2[t] * (acc - m2[t]) * rsqrtf(v2[t] + 1e-5f) + b2[t];
    }
    __syncthreads();
    if (t < 2) {
        float acc = fc3_b[t];
        const float* w = fc3_w + (size_t)t * 256;
        for (int k = 0; k < 256; k++) acc = fmaf(a2[k], w[k], acc);
        lg[t] = acc;
    }
    __syncthreads();
    if (t == 0) {
        float m = fmaxf(lg[0], lg[1]);
        float e0 = expf(lg[0] - m), e1 = expf(lg[1] - m);
        float inv = 1.f / (e0 + e1);
        out[b * 2 + 0] = e0 * inv;
        out[b * 2 + 1] = e1 * inv;
    }
}

// ---------------- launch ----------------
template <typename T>
static T* sym_addr(const void* symbol) {
    void* p = nullptr;
    cudaGetSymbolAddress(&p, symbol);
    return (T*)p;
}

extern "C" void kernel_launch(void* const* d_in, const int* in_sizes, int n_in,
                              void* d_out, int out_size) {
    const float* input   = (const float*)d_in[0];
    const float* W1l     = (const float*)d_in[1];
    const float* b1l     = (const float*)d_in[2];
    const float* W1r     = (const float*)d_in[3];
    const float* Wp1_rel = (const float*)d_in[4];
    const float* bp1_rel = (const float*)d_in[5];
    const float* Wp1_root= (const float*)d_in[6];
    const float* W2l     = (const float*)d_in[7];
    const float* b2l     = (const float*)d_in[8];
    const float* W2r     = (const float*)d_in[9];
    const float* Wp2_rel = (const float*)d_in[10];
    const float* bp2_rel = (const float*)d_in[11];
    const float* Wp2_root= (const float*)d_in[12];
    const float* fc1_w   = (const float*)d_in[13];
    const float* fc1_b   = (const float*)d_in[14];
    const float* bn1_g   = (const float*)d_in[15];
    const float* bn1_b   = (const float*)d_in[16];
    const float* bn1_m   = (const float*)d_in[17];
    const float* bn1_v   = (const float*)d_in[18];
    const float* fc2_w   = (const float*)d_in[19];
    const float* fc2_b   = (const float*)d_in[20];
    const float* bn2_g   = (const float*)d_in[21];
    const float* bn2_b   = (const float*)d_in[22];
    const float* bn2_m   = (const float*)d_in[23];
    const float* bn2_v   = (const float*)d_in[24];
    const float* fc3_w   = (const float*)d_in[25];
    const float* fc3_b   = (const float*)d_in[26];
    float* out = (float*)d_out;

    unsigned char*  pA    = sym_addr<unsigned char>(g_A);
    unsigned short* pNbr  = sym_addr<unsigned short>(g_nbr);
    int*            pDeg  = sym_addr<int>(g_deg);
    float*          pU    = sym_addr<float>(g_U);
    float*          pV    = sym_addr<float>(g_V);
    float*          pSrel = sym_addr<float>(g_srel);
    float*          pSroot= sym_addr<float>(g_sroot);
    float*          pScore= sym_addr<float>(g_score);
    float*          pX1   = sym_addr<float>(g_x1);
    unsigned short* pNbr2 = sym_addr<unsigned short>(g_nbr2);
    int*            pDeg2 = sym_addr<int>(g_deg2);
    float*          pU2   = sym_addr<float>(g_U2);
    float*          pV2   = sym_addr<float>(g_V2);
    float*          pSrel2= sym_addr<float>(g_srel2);
    float*          pSroot2=sym_addr<float>(g_sroot2);
    float*          pScore2=sym_addr<float>(g_score2);

    cudaFuncSetAttribute(k_cov_dp4a, cudaFuncAttributeMaxDynamicSharedMemorySize, COV_SMEM);

    // Stage 0: correlation adjacency (int8 dp4a)
    k_center_q8<<<BB * NNODE / 8, 256>>>(input);
    k_cov_dp4a<<<dim3(8, 8, BB), 256, COV_SMEM>>>(pA);
    k_compact<<<(BB * NNODE * 32 + 255) / 256, 256>>>(pA, pNbr, pDeg, NNODE, BB * NNODE);

    // Stage 1: SAGEConv1 via U = X*Wl^T, V = X*Wr^T (one fused launch), neighbor-mean after
    k_gemmNT128_uv<<<dim3(BB * NNODE / 128, 2), 256>>>(input, W1l, W1r, pU, pV, FIN);
    k_postagg1<<<BB * NNODE / 8, 256>>>(b1l, Wp1_rel, Wp1_root);

    // Stage 2: SAGPool1
    k_score_agg<<<(BB * NNODE * 32 + 255) / 256, 256>>>(pSrel, pSroot, pNbr, pDeg, bp1_rel, pScore, NNODE, BB * NNODE);
    k_topk1<<<BB, NNODE>>>(pScore);
    k_nbr2<<<dim3(KK1 / 8, BB), 256>>>();

    // Stage 3: SAGEConv2 via U2/V2 (one fused launch)
    k_gemmNT64_uv<<<dim3(BB * KK1 / 64, 2), 256>>>(pX1, W2l, W2r, pU2, pV2);
    k_postagg2<<<BB * KK1 / 8, 256>>>(b2l, Wp2_rel, Wp2_root);

    // Stage 4: SAGPool2 + global mean pool
    k_score_agg<<<(BB * KK1 * 32 + 255) / 256, 256>>>(pSrel2, pSroot2, pNbr2, pDeg2, bp2_rel, pScore2, KK1, BB * KK1);
    k_topk2<<<BB, KK1>>>(pScore2);
    k_pool_mean<<<BB, OO>>>();

    // Stage 5: MLP head + softmax
    k_mlp<<<BB, 512>>>(fc1_w, fc1_b, bn1_g, bn1_b, bn1_m, bn1_v,
                       fc2_w, fc2_b, bn2_g, bn2_b, bn2_m, bn2_v,
                       fc3_w, fc3_b, out);
}

// round 9
// speedup vs baseline: 1.0330x; 1.0330x over previous
#include <cuda_runtime.h>
#include <math.h>

#define BB    64
#define NNODE 1024
#define FIN   195
#define HH    128
#define OO    64
#define KK1   512
#define KK2   256
#define QW    64      // padded words per row (256 int8)
#define QWU   49      // used words: ceil(195/4)

// ---------------- scratch (device globals; no allocation allowed) ----------------
__device__ unsigned       g_q8[(size_t)BB*NNODE*QW];
__device__ float          g_s[BB*NNODE];
__device__ unsigned char  g_A[(size_t)BB*NNODE*NNODE];
__device__ unsigned short g_nbr[(size_t)BB*NNODE*NNODE];
__device__ int            g_deg[BB*NNODE];
__device__ float          g_U[(size_t)BB*NNODE*HH];
__device__ float          g_V[(size_t)BB*NNODE*HH];
__device__ float          g_h1[(size_t)BB*NNODE*HH];
__device__ float          g_srel[BB*NNODE];
__device__ float          g_sroot[BB*NNODE];
__device__ float          g_score[BB*NNODE];
__device__ int            g_idx1[BB*KK1];
__device__ float          g_x1[(size_t)BB*KK1*HH];
__device__ unsigned short g_nbr2[(size_t)BB*KK1*KK1];
__device__ int            g_deg2[BB*KK1];
__device__ float          g_U2[(size_t)BB*KK1*OO];
__device__ float          g_V2[(size_t)BB*KK1*OO];
__device__ float          g_h2[(size_t)BB*KK1*OO];
__device__ float          g_srel2[BB*KK1];
__device__ float          g_sroot2[BB*KK1];
__device__ float          g_score2[BB*KK1];
__device__ int            g_idx2[BB*KK2];
__device__ float          g_tanh2[BB*KK2];
__device__ float          g_pool[BB*OO];

// ---------------- 1) center + normalize + int8 quantize (warp per row) ----------------
__global__ void k_center_q8(const float* __restrict__ x) {
    int row = blockIdx.x * 8 + (threadIdx.x >> 5);
    int lane = threadIdx.x & 31;
    const float* xr = x + (size_t)row * FIN;
    float v[8];
    float sum = 0.f;
#pragma unroll
    for (int j = 0; j < 8; j++) {
        int f = lane * 8 + j;
        v[j] = (f < FIN) ? xr[f] : 0.f;
        sum += v[j];
    }
#pragma unroll
    for (int o = 16; o; o >>= 1) sum += __shfl_xor_sync(0xffffffffu, sum, o);
    float mean = sum * (1.0f / FIN);
    float ssq = 0.f;
#pragma unroll
    for (int j = 0; j < 8; j++) {
        int f = lane * 8 + j;
        float c = (f < FIN) ? (v[j] - mean) : 0.f;
        v[j] = c;
        ssq += c * c;
    }
#pragma unroll
    for (int o = 16; o; o >>= 1) ssq += __shfl_xor_sync(0xffffffffu, ssq, o);
    float rinv = rsqrtf(fmaxf(ssq, 1e-12f));
    float mx = 0.f;
#pragma unroll
    for (int j = 0; j < 8; j++) {
        v[j] *= rinv;
        mx = fmaxf(mx, fabsf(v[j]));
    }
#pragma unroll
    for (int o = 16; o; o >>= 1) mx = fmaxf(mx, __shfl_xor_sync(0xffffffffu, mx, o));
    float s = (mx > 0.f) ? 127.f / mx : 0.f;
    int q[8];
#pragma unroll
    for (int j = 0; j < 8; j++) {
        int t = __float2int_rn(v[j] * s);
        q[j] = max(-127, min(127, t));
    }
    unsigned w0 = (q[0] & 0xff) | ((q[1] & 0xff) << 8) | ((q[2] & 0xff) << 16) | ((q[3] & 0xff) << 24);
    unsigned w1 = (q[4] & 0xff) | ((q[5] & 0xff) << 8) | ((q[6] & 0xff) << 16) | ((q[7] & 0xff) << 24);
    unsigned long long pw = (unsigned long long)w0 | ((unsigned long long)w1 << 32);
    *(unsigned long long*)(g_q8 + (size_t)row * QW + lane * 2) = pw;
    if (lane == 0) g_s[row] = s;
}

// ---------------- 2) cov via DP4A int8: A = (dot > 0.5*s_i*s_j) ----------------
// Thread (ty,tx) owns rows ty*8..+7, cols {tx*4..+3} and {64+tx*4..+3} (conflict-free LDS.128)
#define COV_LDW 132
#define COV_SMEM (2 * QW * COV_LDW * 4)   // 67584 B

__global__ void __launch_bounds__(256) k_cov_dp4a(unsigned char* __restrict__ Aout) {
    extern __shared__ unsigned covsm[];
    unsigned* As = covsm;
    unsigned* Bs = covsm + QW * COV_LDW;
    int b = blockIdx.z, bi = blockIdx.x, bj = blockIdx.y;
    if (bj < bi) return;
    int tid = threadIdx.x, tx = tid & 15, ty = tid >> 4;

    const unsigned* qb = g_q8 + (size_t)b * NNODE * QW;
#pragma unroll
    for (int half = 0; half < 2; half++) {
        int rowoff = (half ? bj : bi) * 128;
        unsigned* dst = half ? Bs : As;
        const unsigned* src = qb + (size_t)rowoff * QW;
#pragma unroll
        for (int p = 0; p < 32; p++) {
            int e = tid + p * 256;
            int i = e >> 6, k = e & 63;
            if (k < QWU) dst[k * COV_LDW + i] = src[i * QW + k];
        }
    }
    __syncthreads();

    int acc[8][8];
#pragma unroll
    for (int r = 0; r < 8; r++)
#pragma unroll
        for (int c = 0; c < 8; c++) acc[r][c] = 0;

    for (int kw = 0; kw < QWU; kw++) {
        int a[8], bv[8];
        const unsigned* ap  = As + kw * COV_LDW + ty * 8;
        const unsigned* bp0 = Bs + kw * COV_LDW + tx * 4;
        const unsigned* bp1 = Bs + kw * COV_LDW + 64 + tx * 4;
#pragma unroll
        for (int r = 0; r < 8; r++) a[r] = (int)ap[r];
#pragma unroll
        for (int c = 0; c < 4; c++) { bv[c] = (int)bp0[c]; bv[4 + c] = (int)bp1[c]; }
#pragma unroll
        for (int r = 0; r < 8; r++)
#pragma unroll
            for (int c = 0; c < 8; c++)
                acc[r][c] = __dp4a(a[r], bv[c], acc[r][c]);
    }

    __syncthreads();
    unsigned char* Bt = (unsigned char*)covsm;       // [128][132] bytes
    const float* sb = g_s + b * NNODE;
    float si[8], sj[8];
#pragma unroll
    for (int r = 0; r < 8; r++) si[r] = sb[bi * 128 + ty * 8 + r];
#pragma unroll
    for (int c = 0; c < 4; c++) {
        sj[c]     = sb[bj * 128 + tx * 4 + c];
        sj[4 + c] = sb[bj * 128 + 64 + tx * 4 + c];
    }
#pragma unroll
    for (int r = 0; r < 8; r++) {
        float hs = 0.5f * si[r];
#pragma unroll
        for (int c = 0; c < 4; c++) {
            Bt[(ty * 8 + r) * COV_LDW + tx * 4 + c] =
                ((float)acc[r][c] > hs * sj[c]) ? 1 : 0;
            Bt[(ty * 8 + r) * COV_LDW + 64 + tx * 4 + c] =
                ((float)acc[r][4 + c] > hs * sj[4 + c]) ? 1 : 0;
        }
    }
    __syncthreads();

    {
        int r = tid >> 1, half = (tid & 1) * 64;
        unsigned char* arow = Aout + ((size_t)b * NNODE + bi * 128 + r) * NNODE + bj * 128 + half;
        const unsigned char* srow = Bt + r * COV_LDW + half;
#pragma unroll
        for (int g = 0; g < 4; g++) {
            uint4 vv;
            vv.x = *(const unsigned*)(srow + g * 16 + 0);
            vv.y = *(const unsigned*)(srow + g * 16 + 4);
            vv.z = *(const unsigned*)(srow + g * 16 + 8);
            vv.w = *(const unsigned*)(srow + g * 16 + 12);
            *(uint4*)(arow + g * 16) = vv;
        }
    }
    if (bi != bj) {
        int r = tid >> 1, half = (tid & 1) * 64;
        unsigned char* arow = Aout + ((size_t)b * NNODE + bj * 128 + r) * NNODE + bi * 128 + half;
#pragma unroll
        for (int g = 0; g < 16; g++) {
            unsigned wv = 0;
#pragma unroll
            for (int k2 = 0; k2 < 4; k2++)
                wv |= (unsigned)Bt[(half + g * 4 + k2) * COV_LDW + r] << (8 * k2);
            *(unsigned*)(arow + g * 4) = wv;
        }
    }
}

// ---------------- 3) compact adjacency rows (u32 loads + warp scan) ----------------
__global__ void k_compact(const unsigned char* __restrict__ A, unsigned short* __restrict__ nbr,
                          int* __restrict__ deg, int Nn, int rows) {
    int warp = (blockIdx.x * blockDim.x + threadIdx.x) >> 5;
    int lane = threadIdx.x & 31;
    if (warp >= rows) return;
    const unsigned* ar = (const unsigned*)(A + (size_t)warp * Nn);
    unsigned short* nr = nbr + (size_t)warp * Nn;
    int base = 0;
    for (int it = 0; it < Nn / 128; it++) {
        int w = it * 32 + lane;
        unsigned u = ar[w];
        int c0 = (u & 0xffu) != 0, c1 = (u & 0xff00u) != 0,
            c2 = (u & 0xff0000u) != 0, c3 = (u & 0xff000000u) != 0;
        int cnt = c0 + c1 + c2 + c3;
        int incl = cnt;
#pragma unroll
        for (int o = 1; o < 32; o <<= 1) {
            int t = __shfl_up_sync(0xffffffffu, incl, o);
            if (lane >= o) incl += t;
        }
        int pos = base + incl - cnt;
        int col = w * 4;
        if (c0) nr[pos++] = (unsigned short)(col + 0);
        if (c1) nr[pos++] = (unsigned short)(col + 1);
        if (c2) nr[pos++] = (unsigned short)(col + 2);
        if (c3) nr[pos++] = (unsigned short)(col + 3);
        base += __shfl_sync(0xffffffffu, incl, 31);
    }
    if (lane == 0) deg[warp] = base;
}

// ---------------- 4a) fused U/V GEMM: 128x128 tile, double-buffered, pad 132 ----------------
#define G_LDS 132
__global__ void __launch_bounds__(256) k_gemmNT128_uv(
        const float* __restrict__ X, const float* __restrict__ W0,
        const float* __restrict__ W1, float* __restrict__ U, float* __restrict__ V, int K) {
    __shared__ float As[2][8][G_LDS];
    __shared__ float Bs[2][8][G_LDS];
    const float* W = blockIdx.y ? W1 : W0;
    float* Out = blockIdx.y ? V : U;
    int bx = blockIdx.x;
    int tid = threadIdx.x, tx = tid & 15, ty = tid >> 4;
    float acc[8][8];
#pragma unroll
    for (int r = 0; r < 8; r++)
#pragma unroll
        for (int c = 0; c < 8; c++) acc[r][c] = 0.f;

    const int nk = (K + 7) / 8;

#pragma unroll
    for (int r = 0; r < 4; r++) {
        int e = tid + r * 256;
        int i = e >> 3, k = e & 7;
        float va = (k < K) ? X[(size_t)(bx * 128 + i) * K + k] : 0.f;
        float vb = (k < K) ? W[(size_t)i * K + k] : 0.f;
        As[0][k][i] = va; Bs[0][k][i] = vb;
    }
    __syncthreads();

    for (int t = 0; t < nk; t++) {
        int cur = t & 1, nxt = cur ^ 1;
        if (t + 1 < nk) {
            int kk = (t + 1) * 8;
#pragma unroll
            for (int r = 0; r < 4; r++) {
                int e = tid + r * 256;
                int i = e >> 3, k = e & 7;
                float va = 0.f, vb = 0.f;
                if (kk + k < K) {
                    va = X[(size_t)(bx * 128 + i) * K + kk + k];
                    vb = W[(size_t)i * K + kk + k];
                }
                As[nxt][k][i] = va; Bs[nxt][k][i] = vb;
            }
        }
#pragma unroll
        for (int k = 0; k < 8; k++) {
            float a[8], bv[8];
#pragma unroll
            for (int r = 0; r < 8; r++) a[r] = As[cur][k][ty * 8 + r];
#pragma unroll
            for (int c = 0; c < 4; c++) {
                bv[c]     = Bs[cur][k][tx * 4 + c];
                bv[4 + c] = Bs[cur][k][64 + tx * 4 + c];
            }
#pragma unroll
            for (int r = 0; r < 8; r++)
#pragma unroll
                for (int c = 0; c < 8; c++) acc[r][c] = fmaf(a[r], bv[c], acc[r][c]);
        }
        __syncthreads();
    }
#pragma unroll
    for (int r = 0; r < 8; r++) {
        int gi = bx * 128 + ty * 8 + r;
        float4 v0 = make_float4(acc[r][0], acc[r][1], acc[r][2], acc[r][3]);
        float4 v1 = make_float4(acc[r][4], acc[r][5], acc[r][6], acc[r][7]);
        *(float4*)&Out[(size_t)gi * 128 + tx * 4]      = v0;
        *(float4*)&Out[(size_t)gi * 128 + 64 + tx * 4] = v1;
    }
}

// ---------------- 4b) fused U2/V2 GEMM: out[M x 64] = X[M x 128] * W^T, 64x64 tile ----------------
__global__ void k_gemmNT64_uv(const float* __restrict__ X, const float* __restrict__ W0,
                              const float* __restrict__ W1,
                              float* __restrict__ U, float* __restrict__ V) {
    __shared__ float As[16][68];
    __shared__ float Bs[16][68];
    const float* W = blockIdx.y ? W1 : W0;
    float* Out = blockIdx.y ? V : U;
    int bx = blockIdx.x;
    int tid = threadIdx.x, tx = tid & 15, ty = tid >> 4;
    float acc[4][4];
#pragma unroll
    for (int r = 0; r < 4; r++)
#pragma unroll
        for (int c = 0; c < 4; c++) acc[r][c] = 0.f;

    for (int kk = 0; kk < HH; kk += 16) {
#pragma unroll
        for (int r = 0; r < 4; r++) {
            int e = tid + r * 256;
            int i = e >> 4, k = e & 15;
            As[k][i] = X[(size_t)(bx * 64 + i) * HH + kk + k];
            Bs[k][i] = (i < OO) ? W[(size_t)i * HH + kk + k] : 0.f;
        }
        __syncthreads();
#pragma unroll
        for (int k = 0; k < 16; k++) {
            float a[4], bv[4];
#pragma unroll
            for (int r = 0; r < 4; r++) a[r] = As[k][ty * 4 + r];
#pragma unroll
            for (int c = 0; c < 4; c++) bv[c] = Bs[k][tx * 4 + c];
#pragma unroll
            for (int r = 0; r < 4; r++)
#pragma unroll
                for (int c = 0; c < 4; c++) acc[r][c] = fmaf(a[r], bv[c], acc[r][c]);
        }
        __syncthreads();
    }
#pragma unroll
    for (int r = 0; r < 4; r++) {
        int gi = bx * 64 + ty * 4 + r;
#pragma unroll
        for (int c = 0; c < 4; c++) {
            int gj = tx * 4 + c;
            if (gj < OO) Out[(size_t)gi * OO + gj] = acc[r][c];
        }
    }
}

// ---------------- 5) post-aggregate stage1: h1 = relu(meanN(U) + b + V); + score pre ----------------
__global__ void k_postagg1(const float* __restrict__ bias,
                           const float* __restrict__ Wrel, const float* __restrict__ Wroot) {
    int row = blockIdx.x * 8 + (threadIdx.x >> 5);
    int lane = threadIdx.x & 31;
    int b = row >> 10;
    int dg = g_deg[row];
    const unsigned short* nr = g_nbr + (size_t)row * NNODE;
    float acc[4] = {0.f, 0.f, 0.f, 0.f};
    for (int c = 0; c < dg; c++) {
        const float* Ur = g_U + ((size_t)(b * NNODE + nr[c])) * HH;
#pragma unroll
        for (int k = 0; k < 4; k++) acc[k] += Ur[lane + 32 * k];
    }
    float inv = 1.f / fmaxf((float)dg, 1.f);
    const float* Vr = g_V + (size_t)row * HH;
    float* hr = g_h1 + (size_t)row * HH;
    float sa = 0.f, sr = 0.f;
#pragma unroll
    for (int k = 0; k < 4; k++) {
        int f = lane + 32 * k;
        float h = fmaxf(acc[k] * inv + bias[f] + Vr[f], 0.f);
        hr[f] = h;
        sa = fmaf(h, Wrel[f], sa);
        sr = fmaf(h, Wroot[f], sr);
    }
#pragma unroll
    for (int o = 16; o; o >>= 1) {
        sa += __shfl_down_sync(0xffffffffu, sa, o);
        sr += __shfl_down_sync(0xffffffffu, sr, o);
    }
    if (lane == 0) { g_srel[row] = sa; g_sroot[row] = sr; }
}

// ---------------- 5b) post-aggregate stage2 (F=64) ----------------
__global__ void k_postagg2(const float* __restrict__ bias,
                           const float* __restrict__ Wrel, const float* __restrict__ Wroot) {
    int row = blockIdx.x * 8 + (threadIdx.x >> 5);
    int lane = threadIdx.x & 31;
    int b = row / KK1;
    int dg = g_deg2[row];
    const unsigned short* nr = g_nbr2 + (size_t)row * KK1;
    float acc[2] = {0.f, 0.f};
    for (int c = 0; c < dg; c++) {
        const float* Ur = g_U2 + ((size_t)(b * KK1 + nr[c])) * OO;
#pragma unroll
        for (int k = 0; k < 2; k++) acc[k] += Ur[lane + 32 * k];
    }
    float inv = 1.f / fmaxf((float)dg, 1.f);
    const float* Vr = g_V2 + (size_t)row * OO;
    float* hr = g_h2 + (size_t)row * OO;
    float sa = 0.f, sr = 0.f;
#pragma unroll
    for (int k = 0; k < 2; k++) {
        int f = lane + 32 * k;
        float h = fmaxf(acc[k] * inv + bias[f] + Vr[f], 0.f);
        hr[f] = h;
        sa = fmaf(h, Wrel[f], sa);
        sr = fmaf(h, Wroot[f], sr);
    }
#pragma unroll
    for (int o = 16; o; o >>= 1) {
        sa += __shfl_down_sync(0xffffffffu, sa, o);
        sr += __shfl_down_sync(0xffffffffu, sr, o);
    }
    if (lane == 0) { g_srel2[row] = sa; g_sroot2[row] = sr; }
}

// ---------------- 6) score = sum_{m in N(n)} srel[m] + brel + sroot[n] ----------------
__global__ void k_score_agg(const float* __restrict__ srel, const float* __restrict__ sroot,
                            const unsigned short* __restrict__ nbr, const int* __restrict__ deg,
                            const float* __restrict__ brel, float* __restrict__ score,
                            int Nn, int rows) {
    int warp = (blockIdx.x * blockDim.x + threadIdx.x) >> 5;
    int lane = threadIdx.x & 31;
    if (warp >= rows) return;
    int b = warp / Nn;
    int dg = deg[warp];
    const unsigned short* nr = nbr + (size_t)warp * Nn;
    float a = 0.f;
    for (int c = lane; c < dg; c += 32) a += srel[b * Nn + nr[c]];
    for (int o = 16; o; o >>= 1) a += __shfl_down_sync(0xffffffffu, a, o);
    if (lane == 0) score[warp] = a + brel[0] + sroot[warp];
}

// ---------------- bitonic sort (descending, tie -> smaller idx) ----------------
__device__ __forceinline__ bool prec_cmp(float sa, int ia, float sb, int ib) {
    return (sa > sb) || (sa == sb && ia < ib);
}

template <int NSORT>
__device__ void bitonic_sort(float* s, int* id, int t) {
    for (int k = 2; k <= NSORT; k <<= 1) {
        for (int j = k >> 1; j > 0; j >>= 1) {
            int ixj = t ^ j;
            if (ixj > t) {
                float s1 = s[t], s2 = s[ixj];
                int   i1 = id[t], i2 = id[ixj];
                bool sw;
                if ((t & k) == 0) sw = prec_cmp(s2, i2, s1, i1);
                else              sw = prec_cmp(s1, i1, s2, i2);
                if (sw) { s[t] = s2; s[ixj] = s1; id[t] = i2; id[ixj] = i1; }
            }
            __syncthreads();
        }
    }
}

// ---------------- 7) top-k pool1 + gather x1 ----------------
__global__ void k_topk1(const float* __restrict__ score) {
    __shared__ float s[NNODE];
    __shared__ int   id[NNODE];
    int b = blockIdx.x, t = threadIdx.x;
    s[t] = score[b * NNODE + t];
    id[t] = t;
    __syncthreads();
    bitonic_sort<NNODE>(s, id, t);
    if (t < KK1) {
        g_idx1[b * KK1 + t] = id[t];
        s[t] = tanhf(s[t]);
    }
    __syncthreads();
    const float* h1b = g_h1 + (size_t)b * NNODE * HH;
    float* x1b = g_x1 + (size_t)b * KK1 * HH;
    for (int e = t; e < KK1 * HH; e += NNODE) {
        int k = e >> 7;
        int f = e & 127;
        x1b[e] = h1b[(size_t)id[k] * HH + f] * s[k];
    }
}

// ---------------- 8) fused: nbr2/deg2 directly from A + idx1 ----------------
__global__ void k_nbr2() {
    int b = blockIdx.y;
    int wid = threadIdx.x >> 5, lane = threadIdx.x & 31;
    int i = blockIdx.x * 8 + wid;
    __shared__ int sidx[KK1];
    for (int e = threadIdx.x; e < KK1; e += 256) sidx[e] = g_idx1[b * KK1 + e];
    __syncthreads();
    const unsigned char* ar = g_A + ((size_t)b * NNODE + sidx[i]) * NNODE;
    unsigned short* nr = g_nbr2 + ((size_t)b * KK1 + i) * KK1;
    int cnt = 0;
    for (int base = 0; base < KK1; base += 32) {
        int jj = base + lane;
        unsigned char a = ar[sidx[jj]];
        unsigned mask = __ballot_sync(0xffffffffu, a != 0);
        if (a) nr[cnt + __popc(mask & ((1u << lane) - 1u))] = (unsigned short)jj;
        cnt += __popc(mask);
    }
    if (lane == 0) g_deg2[b * KK1 + i] = cnt;
}

// ---------------- 9) top-k pool2 ----------------
__global__ void k_topk2(const float* __restrict__ score) {
    __shared__ float s[KK1];
    __shared__ int   id[KK1];
    int b = blockIdx.x, t = threadIdx.x;
    s[t] = score[b * KK1 + t];
    id[t] = t;
    __syncthreads();
    bitonic_sort<KK1>(s, id, t);
    if (t < KK2) {
        g_idx2[b * KK2 + t] = id[t];
        g_tanh2[b * KK2 + t] = tanhf(s[t]);
    }
}

// ---------------- 10) gather + scale + global mean pool ----------------
__global__ void k_pool_mean() {
    int b = blockIdx.x, f = threadIdx.x;   // 64 threads
    const float* h2b = g_h2 + (size_t)b * KK1 * OO;
    float acc = 0.f;
    for (int k = 0; k < KK2; k++)
        acc += h2b[(size_t)g_idx2[b * KK2 + k] * OO + f] * g_tanh2[b * KK2 + k];
    g_pool[b * OO + f] = acc * (1.f / KK2);
}

// ---------------- 11) MLP head ----------------
__global__ void k_mlp(const float* __restrict__ fc1_w, const float* __restrict__ fc1_b,
                      const float* __restrict__ g1, const float* __restrict__ b1,
                      const float* __restrict__ m1, const float* __restrict__ v1,
                      const float* __restrict__ fc2_w, const float* __restrict__ fc2_b,
                      const float* __restrict__ g2, const float* __restrict__ b2,
                      const float* __restrict__ m2, const float* __restrict__ v2,
                      const float* __restrict__ fc3_w, const float* __restrict__ fc3_b,
                      float* __restrict__ out) {
    int b = blockIdx.x, t = threadIdx.x;   // 512 threads
    __shared__ float sin[OO];
    __shared__ float a1[512];
    __shared__ float a2[256];
    __shared__ float lg[2];
    if (t < OO) sin[t] = g_pool[b * OO + t];
    __syncthreads();
    {
        float acc = fc1_b[t];
        const float* w = fc1_w + (size_t)t * OO;
        for (int k = 0; k < OO; k++) acc = fmaf(sin[k], w[k], acc);
        acc = fmaxf(acc, 0.f);
        a1[t] = g1[t] * (acc - m1[t]) * rsqrtf(v1[t] + 1e-5f) + b1[t];
    }
    __syncthreads();
    if (t < 256) {
        float acc = fc2_b[t];
        const float* w = fc2_w + (size_t)t * 512;
        for (int k = 0; k < 512; k++) acc = fmaf(a1[k], w[k], acc);
        acc = fmaxf(acc, 0.f);
        a2[t] = g2[t] * (acc - m2[t]) * rsqrtf(v2[t] + 1e-5f) + b2[t];
    }
    __syncthreads();
    if (t < 2) {
        float acc = fc3_b[t];
        const float* w = fc3_w + (size_t)t * 256;
        for (int k = 0; k < 256; k++) acc = fmaf(a2[k], w[k], acc);
        lg[t] = acc;
    }
    __syncthreads();
    if (t == 0) {
        float m = fmaxf(lg[0], lg[1]);
        float e0 = expf(lg[0] - m), e1 = expf(lg[1] - m);
        float inv = 1.f / (e0 + e1);
        out[b * 2 + 0] = e0 * inv;
        out[b * 2 + 1] = e1 * inv;
    }
}

// ---------------- launch ----------------
template <typename T>
static T* sym_addr(const void* symbol) {
    void* p = nullptr;
    cudaGetSymbolAddress(&p, symbol);
    return (T*)p;
}

extern "C" void kernel_launch(void* const* d_in, const int* in_sizes, int n_in,
                              void* d_out, int out_size) {
    const float* input   = (const float*)d_in[0];
    const float* W1l     = (const float*)d_in[1];
    const float* b1l     = (const float*)d_in[2];
    const float* W1r     = (const float*)d_in[3];
    const float* Wp1_rel = (const float*)d_in[4];
    const float* bp1_rel = (const float*)d_in[5];
    const float* Wp1_root= (const float*)d_in[6];
    const float* W2l     = (const float*)d_in[7];
    const float* b2l     = (const float*)d_in[8];
    const float* W2r     = (const float*)d_in[9];
    const float* Wp2_rel = (const float*)d_in[10];
    const float* bp2_rel = (const float*)d_in[11];
    const float* Wp2_root= (const float*)d_in[12];
    const float* fc1_w   = (const float*)d_in[13];
    const float* fc1_b   = (const float*)d_in[14];
    const float* bn1_g   = (const float*)d_in[15];
    const float* bn1_b   = (const float*)d_in[16];
    const float* bn1_m   = (const float*)d_in[17];
    const float* bn1_v   = (const float*)d_in[18];
    const float* fc2_w   = (const float*)d_in[19];
    const float* fc2_b   = (const float*)d_in[20];
    const float* bn2_g   = (const float*)d_in[21];
    const float* bn2_b   = (const float*)d_in[22];
    const float* bn2_m   = (const float*)d_in[23];
    const float* bn2_v   = (const float*)d_in[24];
    const float* fc3_w   = (const float*)d_in[25];
    const float* fc3_b   = (const float*)d_in[26];
    float* out = (float*)d_out;

    unsigned char*  pA    = sym_addr<unsigned char>(g_A);
    unsigned short* pNbr  = sym_addr<unsigned short>(g_nbr);
    int*            pDeg  = sym_addr<int>(g_deg);
    float*          pU    = sym_addr<float>(g_U);
    float*          pV    = sym_addr<float>(g_V);
    float*          pSrel = sym_addr<float>(g_srel);
    float*          pSroot= sym_addr<float>(g_sroot);
    float*          pScore= sym_addr<float>(g_score);
    float*          pX1   = sym_addr<float>(g_x1);
    unsigned short* pNbr2 = sym_addr<unsigned short>(g_nbr2);
    int*            pDeg2 = sym_addr<int>(g_deg2);
    float*          pU2   = sym_addr<float>(g_U2);
    float*          pV2   = sym_addr<float>(g_V2);
    float*          pSrel2= sym_addr<float>(g_srel2);
    float*          pSroot2=sym_addr<float>(g_sroot2);
    float*          pScore2=sym_addr<float>(g_score2);

    cudaFuncSetAttribute(k_cov_dp4a, cudaFuncAttributeMaxDynamicSharedMemorySize, COV_SMEM);

    // Stage 0: correlation adjacency (int8 dp4a)
    k_center_q8<<<BB * NNODE / 8, 256>>>(input);
    k_cov_dp4a<<<dim3(8, 8, BB), 256, COV_SMEM>>>(pA);
    k_compact<<<(BB * NNODE * 32 + 255) / 256, 256>>>(pA, pNbr, pDeg, NNODE, BB * NNODE);

    // Stage 1: SAGEConv1 via U = X*Wl^T, V = X*Wr^T, neighbor-mean after
    k_gemmNT128_uv<<<dim3(BB * NNODE / 128, 2), 256>>>(input, W1l, W1r, pU, pV, FIN);
    k_postagg1<<<BB * NNODE / 8, 256>>>(b1l, Wp1_rel, Wp1_root);

    // Stage 2: SAGPool1
    k_score_agg<<<(BB * NNODE * 32 + 255) / 256, 256>>>(pSrel, pSroot, pNbr, pDeg, bp1_rel, pScore, NNODE, BB * NNODE);
    k_topk1<<<BB, NNODE>>>(pScore);
    k_nbr2<<<dim3(KK1 / 8, BB), 256>>>();

    // Stage 3: SAGEConv2 via U2/V2
    k_gemmNT64_uv<<<dim3(BB * KK1 / 64, 2), 256>>>(pX1, W2l, W2r, pU2, pV2);
    k_postagg2<<<BB * KK1 / 8, 256>>>(b2l, Wp2_rel, Wp2_root);

    // Stage 4: SAGPool2 + global mean pool
    k_score_agg<<<(BB * KK1 * 32 + 255) / 256, 256>>>(pSrel2, pSroot2, pNbr2, pDeg2, bp2_rel, pScore2, KK1, BB * KK1);
    k_topk2<<<BB, KK1>>>(pScore2);
    k_pool_mean<<<BB, OO>>>();

    // Stage 5: MLP head + softmax
    k_mlp<<<BB, 512>>>(fc1_w, fc1_b, bn1_g, bn1_b, bn1_m, bn1_v,
                       fc2_w, fc2_b, bn2_g, bn2_b, bn2_m, bn2_v,
                       fc3_w, fc3_b, out);
}

// round 10
// speedup vs baseline: 1.1190x; 1.0833x over previous
#include <cuda_runtime.h>
#include <math.h>

#define BB    64
#define NNODE 1024
#define FIN   195
#define HH    128
#define OO    64
#define KK1   512
#define KK2   256
#define QW    64
#define QWU   49

// ---------------- scratch ----------------
__device__ unsigned       g_q8[(size_t)BB*NNODE*QW];
__device__ float          g_s[BB*NNODE];
__device__ unsigned char  g_A[(size_t)BB*NNODE*NNODE];
__device__ unsigned short g_nbr[(size_t)BB*NNODE*NNODE];
__device__ int            g_deg[BB*NNODE];
__device__ float          g_U[(size_t)BB*NNODE*HH];
__device__ float          g_V[(size_t)BB*NNODE*HH];
__device__ float          g_h1[(size_t)BB*NNODE*HH];
__device__ float          g_srel[BB*NNODE];
__device__ float          g_sroot[BB*NNODE];
__device__ int            g_idx1[BB*KK1];
__device__ float          g_x1[(size_t)BB*KK1*HH];
__device__ unsigned short g_nbr2[(size_t)BB*KK1*KK1];
__device__ int            g_deg2[BB*KK1];
__device__ float          g_U2[(size_t)BB*KK1*OO];
__device__ float          g_V2[(size_t)BB*KK1*OO];
__device__ float          g_h2[(size_t)BB*KK1*OO];
__device__ float          g_srel2[BB*KK1];
__device__ float          g_sroot2[BB*KK1];

// ---------------- 1) center + normalize + int8 quantize (warp per row) ----------------
__global__ void k_center_q8(const float* __restrict__ x) {
    int row = blockIdx.x * 8 + (threadIdx.x >> 5);
    int lane = threadIdx.x & 31;
    const float* xr = x + (size_t)row * FIN;
    float v[8];
    float sum = 0.f;
#pragma unroll
    for (int j = 0; j < 8; j++) {
        int f = lane * 8 + j;
        v[j] = (f < FIN) ? xr[f] : 0.f;
        sum += v[j];
    }
#pragma unroll
    for (int o = 16; o; o >>= 1) sum += __shfl_xor_sync(0xffffffffu, sum, o);
    float mean = sum * (1.0f / FIN);
    float ssq = 0.f;
#pragma unroll
    for (int j = 0; j < 8; j++) {
        int f = lane * 8 + j;
        float c = (f < FIN) ? (v[j] - mean) : 0.f;
        v[j] = c;
        ssq += c * c;
    }
#pragma unroll
    for (int o = 16; o; o >>= 1) ssq += __shfl_xor_sync(0xffffffffu, ssq, o);
    float rinv = rsqrtf(fmaxf(ssq, 1e-12f));
    float mx = 0.f;
#pragma unroll
    for (int j = 0; j < 8; j++) {
        v[j] *= rinv;
        mx = fmaxf(mx, fabsf(v[j]));
    }
#pragma unroll
    for (int o = 16; o; o >>= 1) mx = fmaxf(mx, __shfl_xor_sync(0xffffffffu, mx, o));
    float s = (mx > 0.f) ? 127.f / mx : 0.f;
    int q[8];
#pragma unroll
    for (int j = 0; j < 8; j++) {
        int t = __float2int_rn(v[j] * s);
        q[j] = max(-127, min(127, t));
    }
    unsigned w0 = (q[0] & 0xff) | ((q[1] & 0xff) << 8) | ((q[2] & 0xff) << 16) | ((q[3] & 0xff) << 24);
    unsigned w1 = (q[4] & 0xff) | ((q[5] & 0xff) << 8) | ((q[6] & 0xff) << 16) | ((q[7] & 0xff) << 24);
    unsigned long long pw = (unsigned long long)w0 | ((unsigned long long)w1 << 32);
    *(unsigned long long*)(g_q8 + (size_t)row * QW + lane * 2) = pw;
    if (lane == 0) g_s[row] = s;
}

// ---------------- 2) cov via DP4A int8 ----------------
#define COV_LDW 132
#define COV_SMEM (2 * QW * COV_LDW * 4)

__global__ void __launch_bounds__(256) k_cov_dp4a(unsigned char* __restrict__ Aout) {
    extern __shared__ unsigned covsm[];
    unsigned* As = covsm;
    unsigned* Bs = covsm + QW * COV_LDW;
    int b = blockIdx.z, bi = blockIdx.x, bj = blockIdx.y;
    if (bj < bi) return;
    int tid = threadIdx.x, tx = tid & 15, ty = tid >> 4;

    const unsigned* qb = g_q8 + (size_t)b * NNODE * QW;
#pragma unroll
    for (int half = 0; half < 2; half++) {
        int rowoff = (half ? bj : bi) * 128;
        unsigned* dst = half ? Bs : As;
        const unsigned* src = qb + (size_t)rowoff * QW;
#pragma unroll
        for (int p = 0; p < 32; p++) {
            int e = tid + p * 256;
            int i = e >> 6, k = e & 63;
            if (k < QWU) dst[k * COV_LDW + i] = src[i * QW + k];
        }
    }
    __syncthreads();

    int acc[8][8];
#pragma unroll
    for (int r = 0; r < 8; r++)
#pragma unroll
        for (int c = 0; c < 8; c++) acc[r][c] = 0;

    for (int kw = 0; kw < QWU; kw++) {
        int a[8], bv[8];
        const unsigned* ap  = As + kw * COV_LDW + ty * 8;
        const unsigned* bp0 = Bs + kw * COV_LDW + tx * 4;
        const unsigned* bp1 = Bs + kw * COV_LDW + 64 + tx * 4;
#pragma unroll
        for (int r = 0; r < 8; r++) a[r] = (int)ap[r];
#pragma unroll
        for (int c = 0; c < 4; c++) { bv[c] = (int)bp0[c]; bv[4 + c] = (int)bp1[c]; }
#pragma unroll
        for (int r = 0; r < 8; r++)
#pragma unroll
            for (int c = 0; c < 8; c++)
                acc[r][c] = __dp4a(a[r], bv[c], acc[r][c]);
    }

    __syncthreads();
    unsigned char* Bt = (unsigned char*)covsm;
    const float* sb = g_s + b * NNODE;
    float si[8], sj[8];
#pragma unroll
    for (int r = 0; r < 8; r++) si[r] = sb[bi * 128 + ty * 8 + r];
#pragma unroll
    for (int c = 0; c < 4; c++) {
        sj[c]     = sb[bj * 128 + tx * 4 + c];
        sj[4 + c] = sb[bj * 128 + 64 + tx * 4 + c];
    }
#pragma unroll
    for (int r = 0; r < 8; r++) {
        float hs = 0.5f * si[r];
#pragma unroll
        for (int c = 0; c < 4; c++) {
            Bt[(ty * 8 + r) * COV_LDW + tx * 4 + c] =
                ((float)acc[r][c] > hs * sj[c]) ? 1 : 0;
            Bt[(ty * 8 + r) * COV_LDW + 64 + tx * 4 + c] =
                ((float)acc[r][4 + c] > hs * sj[4 + c]) ? 1 : 0;
        }
    }
    __syncthreads();

    {
        int r = tid >> 1, half = (tid & 1) * 64;
        unsigned char* arow = Aout + ((size_t)b * NNODE + bi * 128 + r) * NNODE + bj * 128 + half;
        const unsigned char* srow = Bt + r * COV_LDW + half;
#pragma unroll
        for (int g = 0; g < 4; g++) {
            uint4 vv;
            vv.x = *(const unsigned*)(srow + g * 16 + 0);
            vv.y = *(const unsigned*)(srow + g * 16 + 4);
            vv.z = *(const unsigned*)(srow + g * 16 + 8);
            vv.w = *(const unsigned*)(srow + g * 16 + 12);
            *(uint4*)(arow + g * 16) = vv;
        }
    }
    if (bi != bj) {
        int r = tid >> 1, half = (tid & 1) * 64;
        unsigned char* arow = Aout + ((size_t)b * NNODE + bj * 128 + r) * NNODE + bi * 128 + half;
#pragma unroll
        for (int g = 0; g < 16; g++) {
            unsigned wv = 0;
#pragma unroll
            for (int k2 = 0; k2 < 4; k2++)
                wv |= (unsigned)Bt[(half + g * 4 + k2) * COV_LDW + r] << (8 * k2);
            *(unsigned*)(arow + g * 4) = wv;
        }
    }
}

// ---------------- 3) compact adjacency rows (uint4 loads + warp scan) ----------------
__global__ void k_compact(const unsigned char* __restrict__ A, unsigned short* __restrict__ nbr,
                          int* __restrict__ deg, int Nn, int rows) {
    int warp = (blockIdx.x * blockDim.x + threadIdx.x) >> 5;
    int lane = threadIdx.x & 31;
    if (warp >= rows) return;
    const uint4* ar = (const uint4*)(A + (size_t)warp * Nn);
    unsigned short* nr = nbr + (size_t)warp * Nn;
    int base = 0;
    for (int it = 0; it < Nn / 512; it++) {
        uint4 v = ar[it * 32 + lane];
        unsigned wds[4] = {v.x, v.y, v.z, v.w};
        int cnt = 0;
#pragma unroll
        for (int wi = 0; wi < 4; wi++) {
            unsigned u = wds[wi];
            cnt += ((u & 0xffu) != 0) + ((u & 0xff00u) != 0) +
                   ((u & 0xff0000u) != 0) + ((u & 0xff000000u) != 0);
        }
        int incl = cnt;
#pragma unroll
        for (int o = 1; o < 32; o <<= 1) {
            int t = __shfl_up_sync(0xffffffffu, incl, o);
            if (lane >= o) incl += t;
        }
        int pos = base + incl - cnt;
        int colbase = (it * 32 + lane) * 16;
#pragma unroll
        for (int wi = 0; wi < 4; wi++) {
            unsigned u = wds[wi];
            if (u & 0xffu)       nr[pos++] = (unsigned short)(colbase + wi * 4 + 0);
            if (u & 0xff00u)     nr[pos++] = (unsigned short)(colbase + wi * 4 + 1);
            if (u & 0xff0000u)   nr[pos++] = (unsigned short)(colbase + wi * 4 + 2);
            if (u & 0xff000000u) nr[pos++] = (unsigned short)(colbase + wi * 4 + 3);
        }
        base += __shfl_sync(0xffffffffu, incl, 31);
    }
    if (lane == 0) deg[warp] = base;
}

// ---------------- 4a) fused U/V GEMM stage 1: 128x128 tile, pad 132 ----------------
#define G_LDS 132
__global__ void __launch_bounds__(256) k_gemmNT128_uv(
        const float* __restrict__ X, const float* __restrict__ W0,
        const float* __restrict__ W1, float* __restrict__ U, float* __restrict__ V, int K) {
    __shared__ float As[2][8][G_LDS];
    __shared__ float Bs[2][8][G_LDS];
    const float* W = blockIdx.y ? W1 : W0;
    float* Out = blockIdx.y ? V : U;
    int bx = blockIdx.x;
    int tid = threadIdx.x, tx = tid & 15, ty = tid >> 4;
    float acc[8][8];
#pragma unroll
    for (int r = 0; r < 8; r++)
#pragma unroll
        for (int c = 0; c < 8; c++) acc[r][c] = 0.f;

    const int nk = (K + 7) / 8;

#pragma unroll
    for (int r = 0; r < 4; r++) {
        int e = tid + r * 256;
        int i = e >> 3, k = e & 7;
        float va = (k < K) ? X[(size_t)(bx * 128 + i) * K + k] : 0.f;
        float vb = (k < K) ? W[(size_t)i * K + k] : 0.f;
        As[0][k][i] = va; Bs[0][k][i] = vb;
    }
    __syncthreads();

    for (int t = 0; t < nk; t++) {
        int cur = t & 1, nxt = cur ^ 1;
        if (t + 1 < nk) {
            int kk = (t + 1) * 8;
#pragma unroll
            for (int r = 0; r < 4; r++) {
                int e = tid + r * 256;
                int i = e >> 3, k = e & 7;
                float va = 0.f, vb = 0.f;
                if (kk + k < K) {
                    va = X[(size_t)(bx * 128 + i) * K + kk + k];
                    vb = W[(size_t)i * K + kk + k];
                }
                As[nxt][k][i] = va; Bs[nxt][k][i] = vb;
            }
        }
#pragma unroll
        for (int k = 0; k < 8; k++) {
            float a[8], bv[8];
#pragma unroll
            for (int r = 0; r < 8; r++) a[r] = As[cur][k][ty * 8 + r];
#pragma unroll
            for (int c = 0; c < 4; c++) {
                bv[c]     = Bs[cur][k][tx * 4 + c];
                bv[4 + c] = Bs[cur][k][64 + tx * 4 + c];
            }
#pragma unroll
            for (int r = 0; r < 8; r++)
#pragma unroll
                for (int c = 0; c < 8; c++) acc[r][c] = fmaf(a[r], bv[c], acc[r][c]);
        }
        __syncthreads();
    }
#pragma unroll
    for (int r = 0; r < 8; r++) {
        int gi = bx * 128 + ty * 8 + r;
        float4 v0 = make_float4(acc[r][0], acc[r][1], acc[r][2], acc[r][3]);
        float4 v1 = make_float4(acc[r][4], acc[r][5], acc[r][6], acc[r][7]);
        *(float4*)&Out[(size_t)gi * 128 + tx * 4]      = v0;
        *(float4*)&Out[(size_t)gi * 128 + 64 + tx * 4] = v1;
    }
}

// ---------------- 4b) stage-2 GEMM: U2|V2 jointly, 128x128 tile, K=128 ----------------
__global__ void __launch_bounds__(256) k_gemm2_w2(
        const float* __restrict__ X, const float* __restrict__ W2l,
        const float* __restrict__ W2r, float* __restrict__ U2, float* __restrict__ V2) {
    __shared__ float As[2][8][G_LDS];
    __shared__ float Bs[2][8][G_LDS];
    int bx = blockIdx.x;
    int tid = threadIdx.x, tx = tid & 15, ty = tid >> 4;
    float acc[8][8];
#pragma unroll
    for (int r = 0; r < 8; r++)
#pragma unroll
        for (int c = 0; c < 8; c++) acc[r][c] = 0.f;

#pragma unroll
    for (int r = 0; r < 4; r++) {
        int e = tid + r * 256;
        int i = e >> 3, k = e & 7;
        As[0][k][i] = X[(size_t)(bx * 128 + i) * HH + k];
        Bs[0][k][i] = (i < 64) ? W2l[(size_t)i * HH + k] : W2r[(size_t)(i - 64) * HH + k];
    }
    __syncthreads();

    const int nk = HH / 8;   // 16
    for (int t = 0; t < nk; t++) {
        int cur = t & 1, nxt = cur ^ 1;
        if (t + 1 < nk) {
            int kk = (t + 1) * 8;
#pragma unroll
            for (int r = 0; r < 4; r++) {
                int e = tid + r * 256;
                int i = e >> 3, k = e & 7;
                As[nxt][k][i] = X[(size_t)(bx * 128 + i) * HH + kk + k];
                Bs[nxt][k][i] = (i < 64) ? W2l[(size_t)i * HH + kk + k]
                                         : W2r[(size_t)(i - 64) * HH + kk + k];
            }
        }
#pragma unroll
        for (int k = 0; k < 8; k++) {
            float a[8], bv[8];
#pragma unroll
            for (int r = 0; r < 8; r++) a[r] = As[cur][k][ty * 8 + r];
#pragma unroll
            for (int c = 0; c < 4; c++) {
                bv[c]     = Bs[cur][k][tx * 4 + c];
                bv[4 + c] = Bs[cur][k][64 + tx * 4 + c];
            }
#pragma unroll
            for (int r = 0; r < 8; r++)
#pragma unroll
                for (int c = 0; c < 8; c++) acc[r][c] = fmaf(a[r], bv[c], acc[r][c]);
        }
        __syncthreads();
    }
#pragma unroll
    for (int r = 0; r < 8; r++) {
        int gi = bx * 128 + ty * 8 + r;
        float4 v0 = make_float4(acc[r][0], acc[r][1], acc[r][2], acc[r][3]);
        float4 v1 = make_float4(acc[r][4], acc[r][5], acc[r][6], acc[r][7]);
        *(float4*)&U2[(size_t)gi * OO + tx * 4] = v0;
        *(float4*)&V2[(size_t)gi * OO + tx * 4] = v1;
    }
}

// ---------------- 5) post-aggregate stage1 ----------------
__global__ void k_postagg1(const float* __restrict__ bias,
                           const float* __restrict__ Wrel, const float* __restrict__ Wroot) {
    int row = blockIdx.x * 8 + (threadIdx.x >> 5);
    int lane = threadIdx.x & 31;
    int b = row >> 10;
    int dg = g_deg[row];
    const unsigned short* nr = g_nbr + (size_t)row * NNODE;
    float acc[4] = {0.f, 0.f, 0.f, 0.f};
    for (int c = 0; c < dg; c++) {
        const float* Ur = g_U + ((size_t)(b * NNODE + nr[c])) * HH;
#pragma unroll
        for (int k = 0; k < 4; k++) acc[k] += Ur[lane + 32 * k];
    }
    float inv = 1.f / fmaxf((float)dg, 1.f);
    const float* Vr = g_V + (size_t)row * HH;
    float* hr = g_h1 + (size_t)row * HH;
    float sa = 0.f, sr = 0.f;
#pragma unroll
    for (int k = 0; k < 4; k++) {
        int f = lane + 32 * k;
        float h = fmaxf(acc[k] * inv + bias[f] + Vr[f], 0.f);
        hr[f] = h;
        sa = fmaf(h, Wrel[f], sa);
        sr = fmaf(h, Wroot[f], sr);
    }
#pragma unroll
    for (int o = 16; o; o >>= 1) {
        sa += __shfl_down_sync(0xffffffffu, sa, o);
        sr += __shfl_down_sync(0xffffffffu, sr, o);
    }
    if (lane == 0) { g_srel[row] = sa; g_sroot[row] = sr; }
}

// ---------------- 5b) post-aggregate stage2 ----------------
__global__ void k_postagg2(const float* __restrict__ bias,
                           const float* __restrict__ Wrel, const float* __restrict__ Wroot) {
    int row = blockIdx.x * 8 + (threadIdx.x >> 5);
    int lane = threadIdx.x & 31;
    int b = row / KK1;
    int dg = g_deg2[row];
    const unsigned short* nr = g_nbr2 + (size_t)row * KK1;
    float acc[2] = {0.f, 0.f};
    for (int c = 0; c < dg; c++) {
        const float* Ur = g_U2 + ((size_t)(b * KK1 + nr[c])) * OO;
#pragma unroll
        for (int k = 0; k < 2; k++) acc[k] += Ur[lane + 32 * k];
    }
    float inv = 1.f / fmaxf((float)dg, 1.f);
    const float* Vr = g_V2 + (size_t)row * OO;
    float* hr = g_h2 + (size_t)row * OO;
    float sa = 0.f, sr = 0.f;
#pragma unroll
    for (int k = 0; k < 2; k++) {
        int f = lane + 32 * k;
        float h = fmaxf(acc[k] * inv + bias[f] + Vr[f], 0.f);
        hr[f] = h;
        sa = fmaf(h, Wrel[f], sa);
        sr = fmaf(h, Wroot[f], sr);
    }
#pragma unroll
    for (int o = 16; o; o >>= 1) {
        sa += __shfl_down_sync(0xffffffffu, sa, o);
        sr += __shfl_down_sync(0xffffffffu, sr, o);
    }
    if (lane == 0) { g_srel2[row] = sa; g_sroot2[row] = sr; }
}

// ---------------- bitonic sort (descending, tie -> smaller idx) ----------------
__device__ __forceinline__ bool prec_cmp(float sa, int ia, float sb, int ib) {
    return (sa > sb) || (sa == sb && ia < ib);
}

template <int NSORT>
__device__ void bitonic_sort(float* s, int* id, int t) {
    for (int k = 2; k <= NSORT; k <<= 1) {
        for (int j = k >> 1; j > 0; j >>= 1) {
            int ixj = t ^ j;
            if (ixj > t) {
                float s1 = s[t], s2 = s[ixj];
                int   i1 = id[t], i2 = id[ixj];
                bool sw;
                if ((t & k) == 0) sw = prec_cmp(s2, i2, s1, i1);
                else              sw = prec_cmp(s1, i1, s2, i2);
                if (sw) { s[t] = s2; s[ixj] = s1; id[t] = i2; id[ixj] = i1; }
            }
            __syncthreads();
        }
    }
}

// ---------------- 6) fused: score1 + top-k pool1 + gather x1 ----------------
__global__ void k_score_topk1(const float* __restrict__ brel) {
    __shared__ float s[NNODE];
    __shared__ int   id[NNODE];
    int b = blockIdx.x, t = threadIdx.x;   // 1024 threads
    {
        int row = b * NNODE + t;
        int dg = g_deg[row];
        const unsigned short* nr = g_nbr + (size_t)row * NNODE;
        float a = 0.f;
        for (int c = 0; c < dg; c++) a += g_srel[b * NNODE + nr[c]];
        s[t] = a + brel[0] + g_sroot[row];
        id[t] = t;
    }
    __syncthreads();
    bitonic_sort<NNODE>(s, id, t);
    if (t < KK1) {
        g_idx1[b * KK1 + t] = id[t];
        s[t] = tanhf(s[t]);
    }
    __syncthreads();
    const float* h1b = g_h1 + (size_t)b * NNODE * HH;
    float* x1b = g_x1 + (size_t)b * KK1 * HH;
    for (int e = t; e < KK1 * HH; e += NNODE) {
        int k = e >> 7;
        int f = e & 127;
        x1b[e] = h1b[(size_t)id[k] * HH + f] * s[k];
    }
}

// ---------------- 7) fused: nbr2/deg2 from A + idx1 ----------------
__global__ void k_nbr2() {
    int b = blockIdx.y;
    int wid = threadIdx.x >> 5, lane = threadIdx.x & 31;
    int i = blockIdx.x * 8 + wid;
    __shared__ int sidx[KK1];
    for (int e = threadIdx.x; e < KK1; e += 256) sidx[e] = g_idx1[b * KK1 + e];
    __syncthreads();
    const unsigned char* ar = g_A + ((size_t)b * NNODE + sidx[i]) * NNODE;
    unsigned short* nr = g_nbr2 + ((size_t)b * KK1 + i) * KK1;
    int cnt = 0;
    for (int base = 0; base < KK1; base += 32) {
        int jj = base + lane;
        unsigned char a = ar[sidx[jj]];
        unsigned mask = __ballot_sync(0xffffffffu, a != 0);
        if (a) nr[cnt + __popc(mask & ((1u << lane) - 1u))] = (unsigned short)jj;
        cnt += __popc(mask);
    }
    if (lane == 0) g_deg2[b * KK1 + i] = cnt;
}

// ---------------- 8) fused tail: score2 + top-k2 + mean pool + MLP + softmax ----------------
__global__ void __launch_bounds__(512) k_tail2(
        const float* __restrict__ brel,
        const float* __restrict__ fc1_w, const float* __restrict__ fc1_b,
        const float* __restrict__ g1, const float* __restrict__ b1,
        const float* __restrict__ m1, const float* __restrict__ v1,
        const float* __restrict__ fc2_w, const float* __restrict__ fc2_b,
        const float* __restrict__ g2, const float* __restrict__ b2,
        const float* __restrict__ m2, const float* __restrict__ v2,
        const float* __restrict__ fc3_w, const float* __restrict__ fc3_b,
        float* __restrict__ out) {
    __shared__ float s[KK1];
    __shared__ int   id[KK1];
    __shared__ float red[8][OO];
    __shared__ float pooled[OO];
    __shared__ float a1[512];
    __shared__ float a2[256];
    __shared__ float lg[2];
    int b = blockIdx.x, t = threadIdx.x;   // 512 threads

    // score2 for this batch's 512 rows (thread per row)
    {
        int row = b * KK1 + t;
        int dg = g_deg2[row];
        const unsigned short* nr = g_nbr2 + (size_t)row * KK1;
        float a = 0.f;
        for (int c = 0; c < dg; c++) a += g_srel2[b * KK1 + nr[c]];
        s[t] = a + brel[0] + g_sroot2[row];
        id[t] = t;
    }
    __syncthreads();
    bitonic_sort<KK1>(s, id, t);
    if (t < KK2) s[t] = tanhf(s[t]);
    __syncthreads();

    // pooled[f] = (1/KK2) * sum_k h2[id[k]] * tanh(s[k]) ; 8 k-groups x 64 f
    {
        int g = t >> 6, f = t & 63;
        const float* h2b = g_h2 + (size_t)b * KK1 * OO;
        float acc = 0.f;
        for (int k = g * 32; k < g * 32 + 32; k++)
            acc += h2b[(size_t)id[k] * OO + f] * s[k];
        red[g][f] = acc;
    }
    __syncthreads();
    if (t < OO) {
        float acc = 0.f;
#pragma unroll
        for (int g = 0; g < 8; g++) acc += red[g][t];
        pooled[t] = acc * (1.f / KK2);
    }
    __syncthreads();

    // MLP head
    {
        float acc = fc1_b[t];
        const float* w = fc1_w + (size_t)t * OO;
        for (int k = 0; k < OO; k++) acc = fmaf(pooled[k], w[k], acc);
        acc = fmaxf(acc, 0.f);
        a1[t] = g1[t] * (acc - m1[t]) * rsqrtf(v1[t] + 1e-5f) + b1[t];
    }
    __syncthreads();
    if (t < 256) {
        float acc = fc2_b[t];
        const float* w = fc2_w + (size_t)t * 512;
        for (int k = 0; k < 512; k++) acc = fmaf(a1[k], w[k], acc);
        acc = fmaxf(acc, 0.f);
        a2[t] = g2[t] * (acc - m2[t]) * rsqrtf(v2[t] + 1e-5f) + b2[t];
    }
    __syncthreads();
    if (t < 2) {
        float acc = fc3_b[t];
        const float* w = fc3_w + (size_t)t * 256;
        for (int k = 0; k < 256; k++) acc = fmaf(a2[k], w[k], acc);
        lg[t] = acc;
    }
    __syncthreads();
    if (t == 0) {
        float m = fmaxf(lg[0], lg[1]);
        float e0 = expf(lg[0] - m), e1 = expf(lg[1] - m);
        float inv = 1.f / (e0 + e1);
        out[b * 2 + 0] = e0 * inv;
        out[b * 2 + 1] = e1 * inv;
    }
}

// ---------------- launch ----------------
template <typename T>
static T* sym_addr(const void* symbol) {
    void* p = nullptr;
    cudaGetSymbolAddress(&p, symbol);
    return (T*)p;
}

extern "C" void kernel_launch(void* const* d_in, const int* in_sizes, int n_in,
                              void* d_out, int out_size) {
    const float* input   = (const float*)d_in[0];
    const float* W1l     = (const float*)d_in[1];
    const float* b1l     = (const float*)d_in[2];
    const float* W1r     = (const float*)d_in[3];
    const float* Wp1_rel = (const float*)d_in[4];
    const float* bp1_rel = (const float*)d_in[5];
    const float* Wp1_root= (const float*)d_in[6];
    const float* W2l     = (const float*)d_in[7];
    const float* b2l     = (const float*)d_in[8];
    const float* W2r     = (const float*)d_in[9];
    const float* Wp2_rel = (const float*)d_in[10];
    const float* bp2_rel = (const float*)d_in[11];
    const float* Wp2_root= (const float*)d_in[12];
    const float* fc1_w   = (const float*)d_in[13];
    const float* fc1_b   = (const float*)d_in[14];
    const float* bn1_g   = (const float*)d_in[15];
    const float* bn1_b   = (const float*)d_in[16];
    const float* bn1_m   = (const float*)d_in[17];
    const float* bn1_v   = (const float*)d_in[18];
    const float* fc2_w   = (const float*)d_in[19];
    const float* fc2_b   = (const float*)d_in[20];
    const float* bn2_g   = (const float*)d_in[21];
    const float* bn2_b   = (const float*)d_in[22];
    const float* bn2_m   = (const float*)d_in[23];
    const float* bn2_v   = (const float*)d_in[24];
    const float* fc3_w   = (const float*)d_in[25];
    const float* fc3_b   = (const float*)d_in[26];
    float* out = (float*)d_out;

    unsigned char*  pA    = sym_addr<unsigned char>(g_A);
    unsigned short* pNbr  = sym_addr<unsigned short>(g_nbr);
    int*            pDeg  = sym_addr<int>(g_deg);
    float*          pU    = sym_addr<float>(g_U);
    float*          pV    = sym_addr<float>(g_V);
    float*          pX1   = sym_addr<float>(g_x1);
    float*          pU2   = sym_addr<float>(g_U2);
    float*          pV2   = sym_addr<float>(g_V2);

    cudaFuncSetAttribute(k_cov_dp4a, cudaFuncAttributeMaxDynamicSharedMemorySize, COV_SMEM);

    // Stage 0: correlation adjacency
    k_center_q8<<<BB * NNODE / 8, 256>>>(input);
    k_cov_dp4a<<<dim3(8, 8, BB), 256, COV_SMEM>>>(pA);
    k_compact<<<(BB * NNODE * 32 + 255) / 256, 256>>>(pA, pNbr, pDeg, NNODE, BB * NNODE);

    // Stage 1: SAGEConv1
    k_gemmNT128_uv<<<dim3(BB * NNODE / 128, 2), 256>>>(input, W1l, W1r, pU, pV, FIN);
    k_postagg1<<<BB * NNODE / 8, 256>>>(b1l, Wp1_rel, Wp1_root);

    // Stage 2: SAGPool1 (fused score + topk + gather)
    k_score_topk1<<<BB, NNODE>>>(bp1_rel);
    k_nbr2<<<dim3(KK1 / 8, BB), 256>>>();

    // Stage 3: SAGEConv2 (joint U2|V2 GEMM)
    k_gemm2_w2<<<BB * KK1 / 128, 256>>>(pX1, W2l, W2r, pU2, pV2);
    k_postagg2<<<BB * KK1 / 8, 256>>>(b2l, Wp2_rel, Wp2_root);

    // Stage 4+5: fused score2 + topk2 + mean pool + MLP + softmax
    k_tail2<<<BB, 512>>>(bp2_rel,
                         fc1_w, fc1_b, bn1_g, bn1_b, bn1_m, bn1_v,
                         fc2_w, fc2_b, bn2_g, bn2_b, bn2_m, bn2_v,
                         fc3_w, fc3_b, out);
}

// round 11
// speedup vs baseline: 1.2760x; 1.1402x over previous
#include <cuda_runtime.h>
#include <math.h>

#define BB    64
#define NNODE 1024
#define FIN   195
#define HH    128
#define OO    64
#define KK1   512
#define KK2   256
#define QW    64
#define QWU   49

// ---------------- scratch ----------------
__device__ unsigned       g_q8[(size_t)BB*NNODE*QW];
__device__ float          g_s[BB*NNODE];
__device__ unsigned char  g_A[(size_t)BB*NNODE*NNODE];
__device__ unsigned short g_nbr[(size_t)BB*NNODE*NNODE];
__device__ int            g_deg[BB*NNODE];
__device__ float          g_U[(size_t)BB*NNODE*HH];
__device__ float          g_V[(size_t)BB*NNODE*HH];
__device__ float          g_h1[(size_t)BB*NNODE*HH];
__device__ float          g_srel[BB*NNODE];
__device__ float          g_sroot[BB*NNODE];
__device__ int            g_idx1[BB*KK1];
__device__ float          g_x1[(size_t)BB*KK1*HH];
__device__ unsigned short g_nbr2[(size_t)BB*KK1*KK1];
__device__ int            g_deg2[BB*KK1];
__device__ float          g_U2[(size_t)BB*KK1*OO];
__device__ float          g_V2[(size_t)BB*KK1*OO];
__device__ float          g_h2[(size_t)BB*KK1*OO];
__device__ float          g_srel2[BB*KK1];
__device__ float          g_sroot2[BB*KK1];

// ---------------- 1) center + normalize + int8 quantize (warp per row) ----------------
__global__ void k_center_q8(const float* __restrict__ x) {
    int row = blockIdx.x * 8 + (threadIdx.x >> 5);
    int lane = threadIdx.x & 31;
    const float* xr = x + (size_t)row * FIN;
    float v[8];
    float sum = 0.f;
#pragma unroll
    for (int j = 0; j < 8; j++) {
        int f = lane * 8 + j;
        v[j] = (f < FIN) ? xr[f] : 0.f;
        sum += v[j];
    }
#pragma unroll
    for (int o = 16; o; o >>= 1) sum += __shfl_xor_sync(0xffffffffu, sum, o);
    float mean = sum * (1.0f / FIN);
    float ssq = 0.f;
#pragma unroll
    for (int j = 0; j < 8; j++) {
        int f = lane * 8 + j;
        float c = (f < FIN) ? (v[j] - mean) : 0.f;
        v[j] = c;
        ssq += c * c;
    }
#pragma unroll
    for (int o = 16; o; o >>= 1) ssq += __shfl_xor_sync(0xffffffffu, ssq, o);
    float rinv = rsqrtf(fmaxf(ssq, 1e-12f));
    float mx = 0.f;
#pragma unroll
    for (int j = 0; j < 8; j++) {
        v[j] *= rinv;
        mx = fmaxf(mx, fabsf(v[j]));
    }
#pragma unroll
    for (int o = 16; o; o >>= 1) mx = fmaxf(mx, __shfl_xor_sync(0xffffffffu, mx, o));
    float s = (mx > 0.f) ? 127.f / mx : 0.f;
    int q[8];
#pragma unroll
    for (int j = 0; j < 8; j++) {
        int t = __float2int_rn(v[j] * s);
        q[j] = max(-127, min(127, t));
    }
    unsigned w0 = (q[0] & 0xff) | ((q[1] & 0xff) << 8) | ((q[2] & 0xff) << 16) | ((q[3] & 0xff) << 24);
    unsigned w1 = (q[4] & 0xff) | ((q[5] & 0xff) << 8) | ((q[6] & 0xff) << 16) | ((q[7] & 0xff) << 24);
    unsigned long long pw = (unsigned long long)w0 | ((unsigned long long)w1 << 32);
    *(unsigned long long*)(g_q8 + (size_t)row * QW + lane * 2) = pw;
    if (lane == 0) g_s[row] = s;
}

// ---------------- 2) cov via DP4A int8 ----------------
#define COV_LDW 132
#define COV_SMEM (2 * QW * COV_LDW * 4)

__global__ void __launch_bounds__(256) k_cov_dp4a(unsigned char* __restrict__ Aout) {
    extern __shared__ unsigned covsm[];
    unsigned* As = covsm;
    unsigned* Bs = covsm + QW * COV_LDW;
    int b = blockIdx.z, bi = blockIdx.x, bj = blockIdx.y;
    if (bj < bi) return;
    int tid = threadIdx.x, tx = tid & 15, ty = tid >> 4;

    const unsigned* qb = g_q8 + (size_t)b * NNODE * QW;
#pragma unroll
    for (int half = 0; half < 2; half++) {
        int rowoff = (half ? bj : bi) * 128;
        unsigned* dst = half ? Bs : As;
        const unsigned* src = qb + (size_t)rowoff * QW;
#pragma unroll
        for (int p = 0; p < 32; p++) {
            int e = tid + p * 256;
            int i = e >> 6, k = e & 63;
            if (k < QWU) dst[k * COV_LDW + i] = src[i * QW + k];
        }
    }
    __syncthreads();

    int acc[8][8];
#pragma unroll
    for (int r = 0; r < 8; r++)
#pragma unroll
        for (int c = 0; c < 8; c++) acc[r][c] = 0;

    for (int kw = 0; kw < QWU; kw++) {
        int a[8], bv[8];
        const unsigned* ap  = As + kw * COV_LDW + ty * 8;
        const unsigned* bp0 = Bs + kw * COV_LDW + tx * 4;
        const unsigned* bp1 = Bs + kw * COV_LDW + 64 + tx * 4;
#pragma unroll
        for (int r = 0; r < 8; r++) a[r] = (int)ap[r];
#pragma unroll
        for (int c = 0; c < 4; c++) { bv[c] = (int)bp0[c]; bv[4 + c] = (int)bp1[c]; }
#pragma unroll
        for (int r = 0; r < 8; r++)
#pragma unroll
            for (int c = 0; c < 8; c++)
                acc[r][c] = __dp4a(a[r], bv[c], acc[r][c]);
    }

    __syncthreads();
    unsigned char* Bt = (unsigned char*)covsm;
    const float* sb = g_s + b * NNODE;
    float si[8], sj[8];
#pragma unroll
    for (int r = 0; r < 8; r++) si[r] = sb[bi * 128 + ty * 8 + r];
#pragma unroll
    for (int c = 0; c < 4; c++) {
        sj[c]     = sb[bj * 128 + tx * 4 + c];
        sj[4 + c] = sb[bj * 128 + 64 + tx * 4 + c];
    }
#pragma unroll
    for (int r = 0; r < 8; r++) {
        float hs = 0.5f * si[r];
#pragma unroll
        for (int c = 0; c < 4; c++) {
            Bt[(ty * 8 + r) * COV_LDW + tx * 4 + c] =
                ((float)acc[r][c] > hs * sj[c]) ? 1 : 0;
            Bt[(ty * 8 + r) * COV_LDW + 64 + tx * 4 + c] =
                ((float)acc[r][4 + c] > hs * sj[4 + c]) ? 1 : 0;
        }
    }
    __syncthreads();

    {
        int r = tid >> 1, half = (tid & 1) * 64;
        unsigned char* arow = Aout + ((size_t)b * NNODE + bi * 128 + r) * NNODE + bj * 128 + half;
        const unsigned char* srow = Bt + r * COV_LDW + half;
#pragma unroll
        for (int g = 0; g < 4; g++) {
            uint4 vv;
            vv.x = *(const unsigned*)(srow + g * 16 + 0);
            vv.y = *(const unsigned*)(srow + g * 16 + 4);
            vv.z = *(const unsigned*)(srow + g * 16 + 8);
            vv.w = *(const unsigned*)(srow + g * 16 + 12);
            *(uint4*)(arow + g * 16) = vv;
        }
    }
    if (bi != bj) {
        int r = tid >> 1, half = (tid & 1) * 64;
        unsigned char* arow = Aout + ((size_t)b * NNODE + bj * 128 + r) * NNODE + bi * 128 + half;
#pragma unroll
        for (int g = 0; g < 16; g++) {
            unsigned wv = 0;
#pragma unroll
            for (int k2 = 0; k2 < 4; k2++)
                wv |= (unsigned)Bt[(half + g * 4 + k2) * COV_LDW + r] << (8 * k2);
            *(unsigned*)(arow + g * 4) = wv;
        }
    }
}

// ---------------- 3) compact adjacency rows (uint4 loads + warp scan) ----------------
__global__ void k_compact(const unsigned char* __restrict__ A, unsigned short* __restrict__ nbr,
                          int* __restrict__ deg, int Nn, int rows) {
    int warp = (blockIdx.x * blockDim.x + threadIdx.x) >> 5;
    int lane = threadIdx.x & 31;
    if (warp >= rows) return;
    const uint4* ar = (const uint4*)(A + (size_t)warp * Nn);
    unsigned short* nr = nbr + (size_t)warp * Nn;
    int base = 0;
    for (int it = 0; it < Nn / 512; it++) {
        uint4 v = ar[it * 32 + lane];
        unsigned wds[4] = {v.x, v.y, v.z, v.w};
        int cnt = 0;
#pragma unroll
        for (int wi = 0; wi < 4; wi++) {
            unsigned u = wds[wi];
            cnt += ((u & 0xffu) != 0) + ((u & 0xff00u) != 0) +
                   ((u & 0xff0000u) != 0) + ((u & 0xff000000u) != 0);
        }
        int incl = cnt;
#pragma unroll
        for (int o = 1; o < 32; o <<= 1) {
            int t = __shfl_up_sync(0xffffffffu, incl, o);
            if (lane >= o) incl += t;
        }
        int pos = base + incl - cnt;
        int colbase = (it * 32 + lane) * 16;
#pragma unroll
        for (int wi = 0; wi < 4; wi++) {
            unsigned u = wds[wi];
            if (u & 0xffu)       nr[pos++] = (unsigned short)(colbase + wi * 4 + 0);
            if (u & 0xff00u)     nr[pos++] = (unsigned short)(colbase + wi * 4 + 1);
            if (u & 0xff0000u)   nr[pos++] = (unsigned short)(colbase + wi * 4 + 2);
            if (u & 0xff000000u) nr[pos++] = (unsigned short)(colbase + wi * 4 + 3);
        }
        base += __shfl_sync(0xffffffffu, incl, 31);
    }
    if (lane == 0) deg[warp] = base;
}

// ---------------- 4a) U/V GEMM stage 1: register-staged prefetch double buffer ----------------
#define G_LDS 132
__global__ void __launch_bounds__(256, 2) k_gemmNT128_uv(
        const float* __restrict__ X, const float* __restrict__ W0,
        const float* __restrict__ W1, float* __restrict__ U, float* __restrict__ V, int K) {
    __shared__ float As[2][8][G_LDS];
    __shared__ float Bs[2][8][G_LDS];
    const float* W = blockIdx.y ? W1 : W0;
    float* Out = blockIdx.y ? V : U;
    int bx = blockIdx.x;
    int tid = threadIdx.x, tx = tid & 15, ty = tid >> 4;
    float acc[8][8];
#pragma unroll
    for (int r = 0; r < 8; r++)
#pragma unroll
        for (int c = 0; c < 8; c++) acc[r][c] = 0.f;

    const int nk = (K + 7) / 8;

    // element mapping for staging: e = tid + r*256 -> i = e>>3 (row/col), k = e&7
    int si[4], sk[4];
#pragma unroll
    for (int r = 0; r < 4; r++) { int e = tid + r * 256; si[r] = e >> 3; sk[r] = e & 7; }

    // prologue: block 0 straight to smem buffer 0
#pragma unroll
    for (int r = 0; r < 4; r++) {
        float va = (sk[r] < K) ? X[(size_t)(bx * 128 + si[r]) * K + sk[r]] : 0.f;
        float vb = (sk[r] < K) ? W[(size_t)si[r] * K + sk[r]] : 0.f;
        As[0][sk[r]][si[r]] = va; Bs[0][sk[r]][si[r]] = vb;
    }
    __syncthreads();

    float pa[4], pb[4];
    for (int t = 0; t < nk; t++) {
        int cur = t & 1, nxt = cur ^ 1;
        // 1) issue global loads for block t+1 into REGISTERS (no dependent store yet)
        if (t + 1 < nk) {
            int kk = (t + 1) * 8;
#pragma unroll
            for (int r = 0; r < 4; r++) {
                int k = kk + sk[r];
                pa[r] = (k < K) ? X[(size_t)(bx * 128 + si[r]) * K + k] : 0.f;
                pb[r] = (k < K) ? W[(size_t)si[r] * K + k] : 0.f;
            }
        }
        // 2) compute on current buffer (hides the LDG latency)
#pragma unroll
        for (int k = 0; k < 8; k++) {
            float a[8], bv[8];
#pragma unroll
            for (int r = 0; r < 8; r++) a[r] = As[cur][k][ty * 8 + r];
#pragma unroll
            for (int c = 0; c < 4; c++) {
                bv[c]     = Bs[cur][k][tx * 4 + c];
                bv[4 + c] = Bs[cur][k][64 + tx * 4 + c];
            }
#pragma unroll
            for (int r = 0; r < 8; r++)
#pragma unroll
                for (int c = 0; c < 8; c++) acc[r][c] = fmaf(a[r], bv[c], acc[r][c]);
        }
        // 3) commit prefetched registers to the next buffer
        if (t + 1 < nk) {
#pragma unroll
            for (int r = 0; r < 4; r++) {
                As[nxt][sk[r]][si[r]] = pa[r];
                Bs[nxt][sk[r]][si[r]] = pb[r];
            }
        }
        __syncthreads();
    }
#pragma unroll
    for (int r = 0; r < 8; r++) {
        int gi = bx * 128 + ty * 8 + r;
        float4 v0 = make_float4(acc[r][0], acc[r][1], acc[r][2], acc[r][3]);
        float4 v1 = make_float4(acc[r][4], acc[r][5], acc[r][6], acc[r][7]);
        *(float4*)&Out[(size_t)gi * 128 + tx * 4]      = v0;
        *(float4*)&Out[(size_t)gi * 128 + 64 + tx * 4] = v1;
    }
}

// ---------------- 4b) stage-2 GEMM: U2|V2 jointly, register-staged prefetch ----------------
__global__ void __launch_bounds__(256, 2) k_gemm2_w2(
        const float* __restrict__ X, const float* __restrict__ W2l,
        const float* __restrict__ W2r, float* __restrict__ U2, float* __restrict__ V2) {
    __shared__ float As[2][8][G_LDS];
    __shared__ float Bs[2][8][G_LDS];
    int bx = blockIdx.x;
    int tid = threadIdx.x, tx = tid & 15, ty = tid >> 4;
    float acc[8][8];
#pragma unroll
    for (int r = 0; r < 8; r++)
#pragma unroll
        for (int c = 0; c < 8; c++) acc[r][c] = 0.f;

    int si[4], sk[4];
#pragma unroll
    for (int r = 0; r < 4; r++) { int e = tid + r * 256; si[r] = e >> 3; sk[r] = e & 7; }

#pragma unroll
    for (int r = 0; r < 4; r++) {
        As[0][sk[r]][si[r]] = X[(size_t)(bx * 128 + si[r]) * HH + sk[r]];
        Bs[0][sk[r]][si[r]] = (si[r] < 64) ? W2l[(size_t)si[r] * HH + sk[r]]
                                           : W2r[(size_t)(si[r] - 64) * HH + sk[r]];
    }
    __syncthreads();

    const int nk = HH / 8;   // 16
    float pa[4], pb[4];
    for (int t = 0; t < nk; t++) {
        int cur = t & 1, nxt = cur ^ 1;
        if (t + 1 < nk) {
            int kk = (t + 1) * 8;
#pragma unroll
            for (int r = 0; r < 4; r++) {
                int k = kk + sk[r];
                pa[r] = X[(size_t)(bx * 128 + si[r]) * HH + k];
                pb[r] = (si[r] < 64) ? W2l[(size_t)si[r] * HH + k]
                                     : W2r[(size_t)(si[r] - 64) * HH + k];
            }
        }
#pragma unroll
        for (int k = 0; k < 8; k++) {
            float a[8], bv[8];
#pragma unroll
            for (int r = 0; r < 8; r++) a[r] = As[cur][k][ty * 8 + r];
#pragma unroll
            for (int c = 0; c < 4; c++) {
                bv[c]     = Bs[cur][k][tx * 4 + c];
                bv[4 + c] = Bs[cur][k][64 + tx * 4 + c];
            }
#pragma unroll
            for (int r = 0; r < 8; r++)
#pragma unroll
                for (int c = 0; c < 8; c++) acc[r][c] = fmaf(a[r], bv[c], acc[r][c]);
        }
        if (t + 1 < nk) {
#pragma unroll
            for (int r = 0; r < 4; r++) {
                As[nxt][sk[r]][si[r]] = pa[r];
                Bs[nxt][sk[r]][si[r]] = pb[r];
            }
        }
        __syncthreads();
    }
#pragma unroll
    for (int r = 0; r < 8; r++) {
        int gi = bx * 128 + ty * 8 + r;
        float4 v0 = make_float4(acc[r][0], acc[r][1], acc[r][2], acc[r][3]);
        float4 v1 = make_float4(acc[r][4], acc[r][5], acc[r][6], acc[r][7]);
        *(float4*)&U2[(size_t)gi * OO + tx * 4] = v0;
        *(float4*)&V2[(size_t)gi * OO + tx * 4] = v1;
    }
}

// ---------------- 5) post-aggregate stage1 ----------------
__global__ void k_postagg1(const float* __restrict__ bias,
                           const float* __restrict__ Wrel, const float* __restrict__ Wroot) {
    int row = blockIdx.x * 8 + (threadIdx.x >> 5);
    int lane = threadIdx.x & 31;
    int b = row >> 10;
    int dg = g_deg[row];
    const unsigned short* nr = g_nbr + (size_t)row * NNODE;
    float acc[4] = {0.f, 0.f, 0.f, 0.f};
    for (int c = 0; c < dg; c++) {
        const float* Ur = g_U + ((size_t)(b * NNODE + nr[c])) * HH;
#pragma unroll
        for (int k = 0; k < 4; k++) acc[k] += Ur[lane + 32 * k];
    }
    float inv = 1.f / fmaxf((float)dg, 1.f);
    const float* Vr = g_V + (size_t)row * HH;
    float* hr = g_h1 + (size_t)row * HH;
    float sa = 0.f, sr = 0.f;
#pragma unroll
    for (int k = 0; k < 4; k++) {
        int f = lane + 32 * k;
        float h = fmaxf(acc[k] * inv + bias[f] + Vr[f], 0.f);
        hr[f] = h;
        sa = fmaf(h, Wrel[f], sa);
        sr = fmaf(h, Wroot[f], sr);
    }
#pragma unroll
    for (int o = 16; o; o >>= 1) {
        sa += __shfl_down_sync(0xffffffffu, sa, o);
        sr += __shfl_down_sync(0xffffffffu, sr, o);
    }
    if (lane == 0) { g_srel[row] = sa; g_sroot[row] = sr; }
}

// ---------------- 5b) post-aggregate stage2 ----------------
__global__ void k_postagg2(const float* __restrict__ bias,
                           const float* __restrict__ Wrel, const float* __restrict__ Wroot) {
    int row = blockIdx.x * 8 + (threadIdx.x >> 5);
    int lane = threadIdx.x & 31;
    int b = row / KK1;
    int dg = g_deg2[row];
    const unsigned short* nr = g_nbr2 + (size_t)row * KK1;
    float acc[2] = {0.f, 0.f};
    for (int c = 0; c < dg; c++) {
        const float* Ur = g_U2 + ((size_t)(b * KK1 + nr[c])) * OO;
#pragma unroll
        for (int k = 0; k < 2; k++) acc[k] += Ur[lane + 32 * k];
    }
    float inv = 1.f / fmaxf((float)dg, 1.f);
    const float* Vr = g_V2 + (size_t)row * OO;
    float* hr = g_h2 + (size_t)row * OO;
    float sa = 0.f, sr = 0.f;
#pragma unroll
    for (int k = 0; k < 2; k++) {
        int f = lane + 32 * k;
        float h = fmaxf(acc[k] * inv + bias[f] + Vr[f], 0.f);
        hr[f] = h;
        sa = fmaf(h, Wrel[f], sa);
        sr = fmaf(h, Wroot[f], sr);
    }
#pragma unroll
    for (int o = 16; o; o >>= 1) {
        sa += __shfl_down_sync(0xffffffffu, sa, o);
        sr += __shfl_down_sync(0xffffffffu, sr, o);
    }
    if (lane == 0) { g_srel2[row] = sa; g_sroot2[row] = sr; }
}

// ---------------- bitonic sort (descending, tie -> smaller idx) ----------------
__device__ __forceinline__ bool prec_cmp(float sa, int ia, float sb, int ib) {
    return (sa > sb) || (sa == sb && ia < ib);
}

template <int NSORT>
__device__ void bitonic_sort(float* s, int* id, int t) {
    for (int k = 2; k <= NSORT; k <<= 1) {
        for (int j = k >> 1; j > 0; j >>= 1) {
            int ixj = t ^ j;
            if (ixj > t) {
                float s1 = s[t], s2 = s[ixj];
                int   i1 = id[t], i2 = id[ixj];
                bool sw;
                if ((t & k) == 0) sw = prec_cmp(s2, i2, s1, i1);
                else              sw = prec_cmp(s1, i1, s2, i2);
                if (sw) { s[t] = s2; s[ixj] = s1; id[t] = i2; id[ixj] = i1; }
            }
            __syncthreads();
        }
    }
}

// ---------------- 6) fused: score1 + top-k pool1 + gather x1 ----------------
__global__ void k_score_topk1(const float* __restrict__ brel) {
    __shared__ float s[NNODE];
    __shared__ int   id[NNODE];
    int b = blockIdx.x, t = threadIdx.x;   // 1024 threads
    {
        int row = b * NNODE + t;
        int dg = g_deg[row];
        const unsigned short* nr = g_nbr + (size_t)row * NNODE;
        float a = 0.f;
        for (int c = 0; c < dg; c++) a += g_srel[b * NNODE + nr[c]];
        s[t] = a + brel[0] + g_sroot[row];
        id[t] = t;
    }
    __syncthreads();
    bitonic_sort<NNODE>(s, id, t);
    if (t < KK1) {
        g_idx1[b * KK1 + t] = id[t];
        s[t] = tanhf(s[t]);
    }
    __syncthreads();
    const float* h1b = g_h1 + (size_t)b * NNODE * HH;
    float* x1b = g_x1 + (size_t)b * KK1 * HH;
    for (int e = t; e < KK1 * HH; e += NNODE) {
        int k = e >> 7;
        int f = e & 127;
        x1b[e] = h1b[(size_t)id[k] * HH + f] * s[k];
    }
}

// ---------------- 7) fused: nbr2/deg2 from A + idx1 ----------------
__global__ void k_nbr2() {
    int b = blockIdx.y;
    int wid = threadIdx.x >> 5, lane = threadIdx.x & 31;
    int i = blockIdx.x * 8 + wid;
    __shared__ int sidx[KK1];
    for (int e = threadIdx.x; e < KK1; e += 256) sidx[e] = g_idx1[b * KK1 + e];
    __syncthreads();
    const unsigned char* ar = g_A + ((size_t)b * NNODE + sidx[i]) * NNODE;
    unsigned short* nr = g_nbr2 + ((size_t)b * KK1 + i) * KK1;
    int cnt = 0;
    for (int base = 0; base < KK1; base += 32) {
        int jj = base + lane;
        unsigned char a = ar[sidx[jj]];
        unsigned mask = __ballot_sync(0xffffffffu, a != 0);
        if (a) nr[cnt + __popc(mask & ((1u << lane) - 1u))] = (unsigned short)jj;
        cnt += __popc(mask);
    }
    if (lane == 0) g_deg2[b * KK1 + i] = cnt;
}

// ---------------- 8) fused tail: score2 + top-k2 + mean pool + MLP + softmax ----------------
__global__ void __launch_bounds__(512) k_tail2(
        const float* __restrict__ brel,
        const float* __restrict__ fc1_w, const float* __restrict__ fc1_b,
        const float* __restrict__ g1, const float* __restrict__ b1,
        const float* __restrict__ m1, const float* __restrict__ v1,
        const float* __restrict__ fc2_w, const float* __restrict__ fc2_b,
        const float* __restrict__ g2, const float* __restrict__ b2,
        const float* __restrict__ m2, const float* __restrict__ v2,
        const float* __restrict__ fc3_w, const float* __restrict__ fc3_b,
        float* __restrict__ out) {
    __shared__ float s[KK1];
    __shared__ int   id[KK1];
    __shared__ float red[8][OO];
    __shared__ float pooled[OO];
    __shared__ float a1[512];
    __shared__ float a2[256];
    __shared__ float lg[2];
    int b = blockIdx.x, t = threadIdx.x;   // 512 threads

    {
        int row = b * KK1 + t;
        int dg = g_deg2[row];
        const unsigned short* nr = g_nbr2 + (size_t)row * KK1;
        float a = 0.f;
        for (int c = 0; c < dg; c++) a += g_srel2[b * KK1 + nr[c]];
        s[t] = a + brel[0] + g_sroot2[row];
        id[t] = t;
    }
    __syncthreads();
    bitonic_sort<KK1>(s, id, t);
    if (t < KK2) s[t] = tanhf(s[t]);
    __syncthreads();

    {
        int g = t >> 6, f = t & 63;
        const float* h2b = g_h2 + (size_t)b * KK1 * OO;
        float acc = 0.f;
        for (int k = g * 32; k < g * 32 + 32; k++)
            acc += h2b[(size_t)id[k] * OO + f] * s[k];
        red[g][f] = acc;
    }
    __syncthreads();
    if (t < OO) {
        float acc = 0.f;
#pragma unroll
        for (int g = 0; g < 8; g++) acc += red[g][t];
        pooled[t] = acc * (1.f / KK2);
    }
    __syncthreads();

    {
        float acc = fc1_b[t];
        const float* w = fc1_w + (size_t)t * OO;
        for (int k = 0; k < OO; k++) acc = fmaf(pooled[k], w[k], acc);
        acc = fmaxf(acc, 0.f);
        a1[t] = g1[t] * (acc - m1[t]) * rsqrtf(v1[t] + 1e-5f) + b1[t];
    }
    __syncthreads();
    if (t < 256) {
        float acc = fc2_b[t];
        const float* w = fc2_w + (size_t)t * 512;
        for (int k = 0; k < 512; k++) acc = fmaf(a1[k], w[k], acc);
        acc = fmaxf(acc, 0.f);
        a2[t] = g2[t] * (acc - m2[t]) * rsqrtf(v2[t] + 1e-5f) + b2[t];
    }
    __syncthreads();
    if (t < 2) {
        float acc = fc3_b[t];
        const float* w = fc3_w + (size_t)t * 256;
        for (int k = 0; k < 256; k++) acc = fmaf(a2[k], w[k], acc);
        lg[t] = acc;
    }
    __syncthreads();
    if (t == 0) {
        float m = fmaxf(lg[0], lg[1]);
        float e0 = expf(lg[0] - m), e1 = expf(lg[1] - m);
        float inv = 1.f / (e0 + e1);
        out[b * 2 + 0] = e0 * inv;
        out[b * 2 + 1] = e1 * inv;
    }
}

// ---------------- launch ----------------
template <typename T>
static T* sym_addr(const void* symbol) {
    void* p = nullptr;
    cudaGetSymbolAddress(&p, symbol);
    return (T*)p;
}

extern "C" void kernel_launch(void* const* d_in, const int* in_sizes, int n_in,
                              void* d_out, int out_size) {
    const float* input   = (const float*)d_in[0];
    const float* W1l     = (const float*)d_in[1];
    const float* b1l     = (const float*)d_in[2];
    const float* W1r     = (const float*)d_in[3];
    const float* Wp1_rel = (const float*)d_in[4];
    const float* bp1_rel = (const float*)d_in[5];
    const float* Wp1_root= (const float*)d_in[6];
    const float* W2l     = (const float*)d_in[7];
    const float* b2l     = (const float*)d_in[8];
    const float* W2r     = (const float*)d_in[9];
    const float* Wp2_rel = (const float*)d_in[10];
    const float* bp2_rel = (const float*)d_in[11];
    const float* Wp2_root= (const float*)d_in[12];
    const float* fc1_w   = (const float*)d_in[13];
    const float* fc1_b   = (const float*)d_in[14];
    const float* bn1_g   = (const float*)d_in[15];
    const float* bn1_b   = (const float*)d_in[16];
    const float* bn1_m   = (const float*)d_in[17];
    const float* bn1_v   = (const float*)d_in[18];
    const float* fc2_w   = (const float*)d_in[19];
    const float* fc2_b   = (const float*)d_in[20];
    const float* bn2_g   = (const float*)d_in[21];
    const float* bn2_b   = (const float*)d_in[22];
    const float* bn2_m   = (const float*)d_in[23];
    const float* bn2_v   = (const float*)d_in[24];
    const float* fc3_w   = (const float*)d_in[25];
    const float* fc3_b   = (const float*)d_in[26];
    float* out = (float*)d_out;

    unsigned char*  pA    = sym_addr<unsigned char>(g_A);
    unsigned short* pNbr  = sym_addr<unsigned short>(g_nbr);
    int*            pDeg  = sym_addr<int>(g_deg);
    float*          pU    = sym_addr<float>(g_U);
    float*          pV    = sym_addr<float>(g_V);
    float*          pX1   = sym_addr<float>(g_x1);
    float*          pU2   = sym_addr<float>(g_U2);
    float*          pV2   = sym_addr<float>(g_V2);

    cudaFuncSetAttribute(k_cov_dp4a, cudaFuncAttributeMaxDynamicSharedMemorySize, COV_SMEM);

    // Stage 0: correlation adjacency
    k_center_q8<<<BB * NNODE / 8, 256>>>(input);
    k_cov_dp4a<<<dim3(8, 8, BB), 256, COV_SMEM>>>(pA);
    k_compact<<<(BB * NNODE * 32 + 255) / 256, 256>>>(pA, pNbr, pDeg, NNODE, BB * NNODE);

    // Stage 1: SAGEConv1
    k_gemmNT128_uv<<<dim3(BB * NNODE / 128, 2), 256>>>(input, W1l, W1r, pU, pV, FIN);
    k_postagg1<<<BB * NNODE / 8, 256>>>(b1l, Wp1_rel, Wp1_root);

    // Stage 2: SAGPool1
    k_score_topk1<<<BB, NNODE>>>(bp1_rel);
    k_nbr2<<<dim3(KK1 / 8, BB), 256>>>();

    // Stage 3: SAGEConv2
    k_gemm2_w2<<<BB * KK1 / 128, 256>>>(pX1, W2l, W2r, pU2, pV2);
    k_postagg2<<<BB * KK1 / 8, 256>>>(b2l, Wp2_rel, Wp2_root);

    // Stage 4+5: fused tail
    k_tail2<<<BB, 512>>>(bp2_rel,
                         fc1_w, fc1_b, bn1_g, bn1_b, bn1_m, bn1_v,
                         fc2_w, fc2_b, bn2_g, bn2_b, bn2_m, bn2_v,
                         fc3_w, fc3_b, out);
}